// round 13
// baseline (speedup 1.0000x reference)
#include <cuda_runtime.h>
#include <cuda_bf16.h>
#include <math.h>
#include <stdint.h>

// Problem constants
#define Bc 16
#define Nc 5
#define Tc 10
#define Hc 512
#define Ec 250
#define Vc 30000
#define Fc 2048
#define H4 2048
#define H2 1024
#define NTB (Nc*Tc*Bc)   // 800
#define NBLK 128

// packed fp32x2 FMA (SASS FFMA2)
#define FMA2(d, a, b) asm("fma.rn.f32x2 %0, %1, %2, %0;" : "+l"(d) : "l"(a), "l"(b))

__device__ __forceinline__ float f2lo(unsigned long long v) { return __uint_as_float((unsigned)v); }
__device__ __forceinline__ float f2hi(unsigned long long v) { return __uint_as_float((unsigned)(v >> 32)); }
__device__ __forceinline__ unsigned long long splat2(float w) {
    unsigned long long d;
    asm("mov.b64 %0, {%1, %1};" : "=l"(d) : "r"(__float_as_uint(w)));
    return d;
}

// hs bank-swizzled slot address: (k, q) -> byte offset; q = b-group (4 floats)
__device__ __forceinline__ int hs_off(int k, int q) {
    return (((k) << 6) | ((q) << 4)) ^ ((k & 0x1C) << 2);
}

// ---------------- device scratch ----------------
__device__ __align__(16) float g_tmp[Bc*H2];
__device__ __align__(16) float g_tmp2[Bc*H2];
__device__ __align__(16) float g_h0[Bc*Hc];          // [b][k]
__device__ __align__(16) float g_c0[Bc*Hc];          // [b][k]
__device__ __align__(16) float g_hst[4][2][Hc*Bc];   // state h, k-major [k][b]
__device__ __align__(16) float g_cst[4][Hc*Bc];      // state c, k-major
__device__ __align__(16) float g_x0[NTB*Ec];
__device__ __align__(16) float g_xg0[2*NTB*H4];
__device__ __align__(16) float g_x1[Tc*H2*Bc];       // [t][k][b] k-major
__device__ __align__(16) float g_out1[NTB*H2];
__device__ __align__(16) float g_W0T[2*H4*Hc];
__device__ __align__(16) float g_W1T[2*H4*(Hc+H2)];
__device__ __align__(16) __nv_bfloat16 g_Ahi[NTB*H2];
__device__ __align__(16) __nv_bfloat16 g_Alo[NTB*H2];
__device__ __align__(16) __nv_bfloat16 g_Bhi[(size_t)Vc*H2];
__device__ __align__(16) __nv_bfloat16 g_Blo[(size_t)Vc*H2];

__device__ unsigned g_barcnt = 0;
__device__ unsigned g_barsense = 0;

// ---------------- shared sgemm body (64x64 tiles) ----------------
struct TParam { const float* in; float* out; int R; int ostride; };
struct TParams6 { TParam p[6]; };

__device__ __forceinline__ void sgemm_body(
    const float* A, const float* W, const float* bias, float* C,
    int M, int N, int K, int relu, int bm, int bn, int tid,
    float* As, float* Bs)
{
    int tm = (tid >> 4) << 2;
    int tn = (tid & 15) << 2;
    float acc[4][4] = {};
    for (int k0 = 0; k0 < K; k0 += 16) {
        #pragma unroll
        for (int e = 0; e < 4; e++) {
            int idx = tid + e * 256;
            int r = idx >> 4, c = idx & 15;
            int gr = bm + r, gc = k0 + c;
            As[c * 64 + r] = (gr < M && gc < K) ? A[(size_t)gr * K + gc] : 0.f;
        }
        #pragma unroll
        for (int e = 0; e < 4; e++) {
            int idx = tid + e * 256;
            int r = idx >> 6, c = idx & 63;
            int gr = k0 + r, gc = bn + c;
            Bs[r * 64 + c] = (gr < K && gc < N) ? W[(size_t)gr * N + gc] : 0.f;
        }
        __syncthreads();
        #pragma unroll
        for (int kk = 0; kk < 16; kk++) {
            float4 a4 = *(const float4*)&As[kk * 64 + tm];
            float4 b4 = *(const float4*)&Bs[kk * 64 + tn];
            float a[4] = {a4.x, a4.y, a4.z, a4.w};
            float b[4] = {b4.x, b4.y, b4.z, b4.w};
            #pragma unroll
            for (int i = 0; i < 4; i++)
                #pragma unroll
                for (int j = 0; j < 4; j++)
                    acc[i][j] = fmaf(a[i], b[j], acc[i][j]);
        }
        __syncthreads();
    }
    #pragma unroll
    for (int i = 0; i < 4; i++) {
        int gm = bm + tm + i;
        if (gm >= M) continue;
        #pragma unroll
        for (int j = 0; j < 4; j++) {
            int gn = bn + tn + j;
            if (gn >= N) continue;
            float v = acc[i][j] + bias[gn];
            if (relu) v = fmaxf(v, 0.f);
            C[(size_t)gm * N + gn] = v;
        }
    }
}

// ================= pre1: transposes + MLP stage1 + gather + convB =================
#define P1_TRANS 12288           // 6 * 64 * 32
#define P1_MLP   (P1_TRANS + 32)
#define P1_GATH  (P1_MLP + 800)
#define P1_TOTAL (P1_GATH + 30016)   // 938*32 convB blocks

__global__ __launch_bounds__(256) void pre1(
    TParams6 tp,
    const float* __restrict__ img,
    const float* __restrict__ Wh1, const float* __restrict__ bh1,
    const float* __restrict__ Wc1, const float* __restrict__ bc1,
    const int* __restrict__ caps, const float* __restrict__ emb,
    const float* __restrict__ Wfc)
{
    __shared__ float sh[2048];
    int id = blockIdx.x, tid = threadIdx.x;
    int tx = tid & 31, ty = tid >> 5;

    if (id < P1_TRANS) {
        int which = id / 2048, rem = id % 2048;
        int bx = rem & 63, by = rem >> 6;
        TParam p = tp.p[which];
        int c0 = bx * 32, r0 = by * 32;
        if (r0 >= p.R) return;
        for (int j = ty; j < 32; j += 8) {
            int r = r0 + j, c = c0 + tx;
            sh[j * 33 + tx] = (r < p.R) ? p.in[(size_t)r * H4 + c] : 0.f;
        }
        __syncthreads();
        for (int j = ty; j < 32; j += 8) {
            int c = c0 + j, r = r0 + tx;
            if (r < p.R) p.out[(size_t)c * p.ostride + r] = sh[tx * 33 + j];
        }
    } else if (id < P1_MLP) {
        int sub = id - P1_TRANS;
        int z = sub >> 4, bx = sub & 15;
        sgemm_body(img, z ? Wc1 : Wh1, z ? bc1 : bh1, z ? g_tmp2 : g_tmp,
                   Bc, H2, Fc, 1, 0, bx * 64, tid, sh, sh + 1024);
    } else if (id < P1_GATH) {
        int rid = id - P1_MLP;
        int b = rid & 15;
        int nt = rid >> 4;
        int n = nt / Tc, t = nt % Tc;
        int tok = caps[b * (Nc * Tc) + n * Tc + t];
        const float* e = emb + (size_t)tok * Ec;
        float* o = g_x0 + (size_t)rid * Ec;
        for (int i = tid; i < Ec; i += 256) o[i] = e[i];
    } else {
        int sub = id - P1_GATH;
        int n0 = (sub % 938) * 32, k0 = (sub / 938) * 32;
        for (int j = ty; j < 32; j += 8) {
            int k = k0 + j, n = n0 + tx;
            sh[j * 33 + tx] = (n < Vc) ? Wfc[(size_t)k * Vc + n] : 0.f;
        }
        __syncthreads();
        for (int j = ty; j < 32; j += 8) {
            int n = n0 + j, k = k0 + tx;
            if (n < Vc) {
                float v = sh[tx * 33 + j];
                __nv_bfloat16 h = __float2bfloat16(v);
                g_Bhi[(size_t)n * H2 + k] = h;
                g_Blo[(size_t)n * H2 + k] = __float2bfloat16(v - __bfloat162float(h));
            }
        }
    }
}

// ================= pre2: MLP stage2 (dual via z) =================
__global__ __launch_bounds__(256) void pre2k(
    const float* __restrict__ Wh2, const float* __restrict__ bh2,
    const float* __restrict__ Wc2, const float* __restrict__ bc2)
{
    __shared__ float sh[2048];
    int z = blockIdx.z;
    sgemm_body(z ? g_tmp2 : g_tmp, z ? Wc2 : Wh2, z ? bc2 : bh2, z ? g_c0 : g_h0,
               Bc, Hc, H2, 1, 0, blockIdx.x * 64, threadIdx.x, sh, sh + 1024);
}

// ================= pre3: xg0 GEMM (z=0,1) + state broadcast k-major (z=2) =================
__global__ __launch_bounds__(256) void pre3(
    const float* __restrict__ B0, const float* __restrict__ bias0,
    const float* __restrict__ B1, const float* __restrict__ bias1)
{
    __shared__ __align__(16) float As[2][16][128];
    __shared__ __align__(16) float Bs[2][16][256];

    if (blockIdx.z == 2) {
        int lin = blockIdx.y * 16 + blockIdx.x;
        if (lin < 32) {
            int i = lin * 256 + threadIdx.x;   // i = k*16 + b
            int k = i >> 4, b = i & 15;
            float h = g_h0[b * Hc + k];
            float c = g_c0[b * Hc + k];
            #pragma unroll
            for (int s = 0; s < 4; s++) {
                g_hst[s][0][i] = h;
                g_cst[s][i]    = c;
            }
        }
        return;
    }

    const float* A = g_x0;
    const float* B = blockIdx.z ? B1 : B0;
    const float* bias = blockIdx.z ? bias1 : bias0;
    float* C = blockIdx.z ? (g_xg0 + (size_t)NTB * H4) : g_xg0;
    const int M = NTB, N = H4, K = Ec;

    int tid = threadIdx.x;
    int bm = blockIdx.y * 128, bn = blockIdx.x * 128;
    int tx = tid & 15, ty = tid >> 4;
    int ar = tid >> 2, ac = (tid & 3) * 4;
    int br = tid >> 5, bc = (tid & 31) * 4;

    unsigned long long acc[4][8];
    #pragma unroll
    for (int i = 0; i < 4; i++)
        #pragma unroll
        for (int j = 0; j < 8; j++) acc[i][j] = 0ull;

    float a0[4], a1[4], b0[4], b1[4];
    int KT = (K + 15) / 16;

#define LOADTILE(KT_) do {                                                        \
    int k0 = (KT_) * 16;                                                          \
    int gr0 = bm + ar, gr1 = bm + ar + 64;                                        \
    _Pragma("unroll") for (int j = 0; j < 4; j++) {                               \
        int gk = k0 + ac + j;                                                     \
        bool ok = (gk < K);                                                       \
        a0[j] = (ok && gr0 < M) ? A[(size_t)gr0 * K + gk] : 0.f;                  \
        a1[j] = (ok && gr1 < M) ? A[(size_t)gr1 * K + gk] : 0.f;                  \
    }                                                                             \
    int gk0 = k0 + br, gk1 = k0 + br + 8;                                         \
    _Pragma("unroll") for (int j = 0; j < 4; j++) {                               \
        int gc = bn + bc + j;                                                     \
        b0[j] = (gk0 < K) ? B[(size_t)gk0 * N + gc] : 0.f;                        \
        b1[j] = (gk1 < K) ? B[(size_t)gk1 * N + gc] : 0.f;                        \
    }                                                                             \
} while (0)

#define STORETILE(BUF_) do {                                                      \
    _Pragma("unroll") for (int j = 0; j < 4; j++) {                               \
        As[BUF_][ac + j][ar]      = a0[j];                                        \
        As[BUF_][ac + j][ar + 64] = a1[j];                                        \
        Bs[BUF_][br][(bc + j) * 2]         = b0[j];                               \
        Bs[BUF_][br][(bc + j) * 2 + 1]     = b0[j];                               \
        Bs[BUF_][br + 8][(bc + j) * 2]     = b1[j];                               \
        Bs[BUF_][br + 8][(bc + j) * 2 + 1] = b1[j];                               \
    }                                                                             \
} while (0)

    LOADTILE(0);
    STORETILE(0);
    __syncthreads();

    for (int kt = 0; kt < KT; kt++) {
        int cur = kt & 1;
        if (kt + 1 < KT) LOADTILE(kt + 1);
        #pragma unroll
        for (int k = 0; k < 16; k++) {
            unsigned long long a2[4], b2[8];
            #pragma unroll
            for (int i = 0; i < 4; i++)
                a2[i] = *(const unsigned long long*)&As[cur][k][ty * 8 + 2 * i];
            #pragma unroll
            for (int j = 0; j < 8; j++)
                b2[j] = *(const unsigned long long*)&Bs[cur][k][(tx + 16 * j) * 2];
            #pragma unroll
            for (int i = 0; i < 4; i++)
                #pragma unroll
                for (int j = 0; j < 8; j++)
                    FMA2(acc[i][j], a2[i], b2[j]);
        }
        if (kt + 1 < KT) STORETILE(cur ^ 1);
        __syncthreads();
    }

    #pragma unroll
    for (int j = 0; j < 8; j++) {
        int col = bn + tx + 16 * j;
        float bb = bias[col];
        #pragma unroll
        for (int i = 0; i < 4; i++) {
            int r0 = bm + ty * 8 + 2 * i;
            float lo = f2lo(acc[i][j]) + bb;
            float hi = f2hi(acc[i][j]) + bb;
            if (r0 < M)     C[(size_t)r0 * N + col] = lo;
            if (r0 + 1 < M) C[(size_t)(r0 + 1) * N + col] = hi;
        }
    }
#undef LOADTILE
#undef STORETILE
}

// ================= persistent recurrent kernel =================
__device__ __forceinline__ void grid_bar(unsigned& sense)
{
    __syncthreads();
    sense ^= 1;
    if (threadIdx.x == 0) {
        __threadfence();
        unsigned old = atomicAdd(&g_barcnt, 1);
        if (old == NBLK - 1) {
            g_barcnt = 0;
            __threadfence();
            atomicExch(&g_barsense, sense);
        } else {
            while (*(volatile unsigned*)&g_barsense != sense) __nanosleep(32);
        }
        __threadfence();
    }
    __syncthreads();
}

// red layout: row (0..31) stride 2560 B; ksub (0..31) stride 80 B; b (0..15) * 4 B
#define RED_ROWSTRIDE 2560
#define RED_BYTES (32 * RED_ROWSTRIDE)     // 81920

template<int LAYER>
__device__ __forceinline__ void lstm_do_step(
    int tid, int dir, int bkid, int ksub, int bs, int rg,
    char* hsb, char* redb,
    int n, int tok, int par,
    const float* bias1, const float* xg0d, unsigned& sense)
{
    const int K = LAYER ? (Hc + H2) : Hc;
    int slot = LAYER ? (2 + dir) : dir;
    const float* hglob = &g_hst[slot][par][0];
    float* hout = &g_hst[slot][par ^ 1][0];
    float* cst  = &g_cst[slot][0];
    const float* WT = LAYER ? (g_W1T + (size_t)dir * H4 * (Hc + H2))
                            : (g_W0T + (size_t)dir * H4 * Hc);

    // stage A: stage h (and x1 for layer1) into bank-swizzled smem
    {
        const float* x1g = g_x1 + (size_t)tok * H2 * Bc;
        int nf4 = K * 4;
        for (int idx = tid; idx < nf4; idx += 512) {
            int k = idx >> 2, q = idx & 3;
            float4 v;
            if (!LAYER || k < Hc) v = *(const float4*)&hglob[k * Bc + q * 4];
            else                  v = *(const float4*)&x1g[(size_t)(k - Hc) * Bc + q * 4];
            *(float4*)(hsb + hs_off(k, q)) = v;
        }
    }
    __syncthreads();

    // stage B: 8 rows per thread, 32 k-slices; 16 warps hide latency (no manual prefetch)
    const float4* pw = (const float4*)(WT + (size_t)(rg * Hc + bkid * 8) * K);
    const int RS = K / 4;            // f4 row stride
    const int KI = K / 128;          // chunks (4 or 12)

    unsigned long long acc0[8], acc1[8];
    #pragma unroll
    for (int j = 0; j < 8; j++) { acc0[j] = 0ull; acc1[j] = 0ull; }

    #pragma unroll 2
    for (int i = 0; i < KI; i++) {
        float4 cur[8];
        int f4i = i * 32 + ksub;
        #pragma unroll
        for (int j = 0; j < 8; j++) cur[j] = pw[j * RS + f4i];
        int kb = i * 128 + ksub * 4;
        #pragma unroll
        for (int kk = 0; kk < 4; kk++) {
            ulonglong2 hv = *(const ulonglong2*)(hsb + hs_off(kb + kk, bs));
            #pragma unroll
            for (int j = 0; j < 8; j++) {
                unsigned long long s = splat2(((const float*)&cur[j])[kk]);
                FMA2(acc0[j], s, hv.x);
                FMA2(acc1[j], s, hv.y);
            }
        }
    }

    // stage C: dump partials; acc0 = (b0,b1), acc1 = (b2,b3) for each row
    #pragma unroll
    for (int j = 0; j < 8; j++) {
        int row = rg * 8 + j;
        float4 v = make_float4(f2lo(acc0[j]), f2hi(acc0[j]),
                               f2lo(acc1[j]), f2hi(acc1[j]));
        *(float4*)(redb + row * RED_ROWSTRIDE + ksub * 80 + bs * 16) = v;
    }
    __syncthreads();

    // stage D: reduce over 32 ksub + nonlinearity + state update
    if (tid < 128) {
        int ko_l = tid & 7, b = tid >> 3;
        int ko = bkid * 8 + ko_l;
        float gsum[4];
        #pragma unroll
        for (int g = 0; g < 4; g++) {
            int row = g * 8 + ko_l;
            const char* base = redb + row * RED_ROWSTRIDE;
            float ss = 0.f;
            #pragma unroll
            for (int ks = 0; ks < 32; ks++)
                ss += ((const float*)(base + ks * 80))[b];
            gsum[g] = ss;
        }
        float pi, pf, pg, po;
        if (LAYER) {
            pi = bias1[ko]; pf = bias1[512 + ko];
            pg = bias1[1024 + ko]; po = bias1[1536 + ko];
        } else {
            const float* xg = xg0d + ((size_t)(n * Tc + tok) * Bc + b) * H4 + ko;
            pi = xg[0]; pf = xg[512]; pg = xg[1024]; po = xg[1536];
        }
        float gi = gsum[0] + pi, gf = gsum[1] + pf, gg = gsum[2] + pg, go = gsum[3] + po;
        float si = 1.f / (1.f + expf(-gi));
        float sf = 1.f / (1.f + expf(-gf));
        float so = 1.f / (1.f + expf(-go));
        int idx = ko * Bc + b;
        float cn = sf * cst[idx] + si * tanhf(gg);
        float hn = so * tanhf(cn);
        cst[idx]  = cn;
        hout[idx] = hn;
        if (LAYER) {
            g_out1[((size_t)(n * Tc + tok) * Bc + b) * H2 + dir * Hc + ko] = hn;
        } else {
            g_x1[((size_t)tok * H2 + dir * Hc + ko) * Bc + b] = hn;
        }
    }
    grid_bar(sense);
}

#define HS_BYTES ((Hc + H2) * 64)          // 98304
#define LSTM_SMEM (HS_BYTES + RED_BYTES)   // 180224

__global__ __launch_bounds__(512, 1) void lstm_persist(
    const float* __restrict__ b1f_, const float* __restrict__ b1b_)
{
    extern __shared__ __align__(16) char smemc[];
    char* hsb  = smemc;
    char* redb = smemc + HS_BYTES;

    int tid = threadIdx.x, bid = blockIdx.x;
    int dir = bid >> 6, bkid = bid & 63;
    // warp layout: bits0-2 = ksub_l, bits3-4 = bs (duplicates in-warp), bits5-6 = ksub_mid, bit7+ = rg
    int ksub = (tid & 7) | (((tid >> 5) & 3) << 3);   // 0..31
    int bs   = (tid >> 3) & 3;
    int rg   = tid >> 7;                               // 0..3

    const float* bias1 = dir ? b1b_ : b1f_;
    const float* xg0d  = g_xg0 + (size_t)dir * NTB * H4;

    unsigned sense = 0;
    int p0 = 0, p1 = 0;

    for (int t = 0; t < Tc; t++) {
        for (int n = 0; n < Nc; n++) {
            int L = t + 1;
            for (int s = 0; s < L; s++) {
                int tok = dir ? (L - 1 - s) : s;
                lstm_do_step<0>(tid, dir, bkid, ksub, bs, rg, hsb, redb,
                                n, tok, p0, bias1, xg0d, sense);
                p0 ^= 1;
            }
            for (int s = 0; s < L; s++) {
                int tok = dir ? (L - 1 - s) : s;
                lstm_do_step<1>(tid, dir, bkid, ksub, bs, rg, hsb, redb,
                                n, tok, p1, bias1, xg0d, sense);
                p1 ^= 1;
            }
        }
    }

    // fused convA: out1 -> bf16 hi/lo (all out1 writes visible after final grid_bar)
    for (int i = bid * 512 + tid; i < NTB * H2; i += NBLK * 512) {
        float v = g_out1[i];
        __nv_bfloat16 h = __float2bfloat16(v);
        g_Ahi[i] = h;
        g_Alo[i] = __float2bfloat16(v - __bfloat162float(h));
    }
}

// ================= bf16-split mma.sync FC =================
#define FCBM 128
#define FCBN 128
#define FCBK 64
#define PADK 72
#define FC_SMEM (4 * FCBM * PADK * 2)

__device__ __forceinline__ void mma16816(
    float& c0, float& c1, float& c2, float& c3,
    uint32_t a0, uint32_t a1, uint32_t a2, uint32_t a3,
    uint32_t b0, uint32_t b1)
{
    asm volatile(
        "mma.sync.aligned.m16n8k16.row.col.f32.bf16.bf16.f32 "
        "{%0,%1,%2,%3}, {%4,%5,%6,%7}, {%8,%9}, {%0,%1,%2,%3};"
        : "+f"(c0), "+f"(c1), "+f"(c2), "+f"(c3)
        : "r"(a0), "r"(a1), "r"(a2), "r"(a3), "r"(b0), "r"(b1));
}

__global__ __launch_bounds__(256) void fc_wmma(
    const float* __restrict__ bias, float* __restrict__ out)
{
    extern __shared__ __align__(16) __nv_bfloat16 sm[];
    __nv_bfloat16* sAh = sm;
    __nv_bfloat16* sAl = sm + FCBM * PADK;
    __nv_bfloat16* sBh = sm + 2 * FCBM * PADK;
    __nv_bfloat16* sBl = sm + 3 * FCBM * PADK;

    int tid = threadIdx.x;
    int wid = tid >> 5, lane = tid & 31;
    int g = lane >> 2, q = lane & 3;
    int wm = wid & 3, wn = wid >> 2;
    int bm = blockIdx.y * FCBM, bn = blockIdx.x * FCBN;

    const uint4* A4h = (const uint4*)g_Ahi;
    const uint4* A4l = (const uint4*)g_Alo;
    const uint4* B4h = (const uint4*)g_Bhi;
    const uint4* B4l = (const uint4*)g_Blo;
    const uint4 z4 = make_uint4(0, 0, 0, 0);

    float acc[2][8][4];
    #pragma unroll
    for (int i = 0; i < 2; i++)
        #pragma unroll
        for (int j = 0; j < 8; j++)
            #pragma unroll
            for (int e = 0; e < 4; e++) acc[i][j][e] = 0.f;

    const uint32_t* sA32h = (const uint32_t*)sAh;
    const uint32_t* sA32l = (const uint32_t*)sAl;
    const uint32_t* sB32h = (const uint32_t*)sBh;
    const uint32_t* sB32l = (const uint32_t*)sBl;

    for (int kc = 0; kc < H2 / FCBK; kc++) {
        __syncthreads();
        #pragma unroll
        for (int it = 0; it < 4; it++) {
            int idx = tid + it * 256;
            int m = idx >> 3, kg = idx & 7;
            int gm = bm + m;
            size_t gi = (size_t)gm * (H2 / 8) + kc * 8 + kg;
            uint4 vh = z4, vl = z4;
            if (gm < NTB) { vh = A4h[gi]; vl = A4l[gi]; }
            *(uint4*)&sAh[m * PADK + kg * 8] = vh;
            *(uint4*)&sAl[m * PADK + kg * 8] = vl;
        }
        #pragma unroll
        for (int it = 0; it < 4; it++) {
            int idx = tid + it * 256;
            int n = idx >> 3, kg = idx & 7;
            int gn = bn + n;
            uint4 vh = z4, vl = z4;
            if (gn < Vc) {
                size_t gi = (size_t)gn * (H2 / 8) + kc * 8 + kg;
                vh = B4h[gi]; vl = B4l[gi];
            }
            *(uint4*)&sBh[n * PADK + kg * 8] = vh;
            *(uint4*)&sBl[n * PADK + kg * 8] = vl;
        }
        __syncthreads();

        #pragma unroll
        for (int ks = 0; ks < 4; ks++) {
            uint32_t ah[2][4], al[2][4];
            #pragma unroll
            for (int mi = 0; mi < 2; mi++) {
                int r0 = (wm * 32 + mi * 16 + g) * (PADK / 2);
                int r8 = r0 + 8 * (PADK / 2);
                int w0 = ks * 8 + q, w4 = w0 + 4;
                ah[mi][0] = sA32h[r0 + w0]; ah[mi][1] = sA32h[r8 + w0];
                ah[mi][2] = sA32h[r0 + w4]; ah[mi][3] = sA32h[r8 + w4];
                al[mi][0] = sA32l[r0 + w0]; al[mi][1] = sA32l[r8 + w0];
                al[mi][2] = sA32l[r0 + w4]; al[mi][3] = sA32l[r8 + w4];
            }
            #pragma unroll
            for (int ni = 0; ni < 8; ni++) {
                int nr = (wn * 64 + ni * 8 + g) * (PADK / 2);
                int w0 = ks * 8 + q, w4 = w0 + 4;
                uint32_t bh0 = sB32h[nr + w0], bh1 = sB32h[nr + w4];
                uint32_t bl0 = sB32l[nr + w0], bl1 = sB32l[nr + w4];
                #pragma unroll
                for (int mi = 0; mi < 2; mi++) {
                    float* c = acc[mi][ni];
                    mma16816(c[0], c[1], c[2], c[3],
                             ah[mi][0], ah[mi][1], ah[mi][2], ah[mi][3], bh0, bh1);
                    mma16816(c[0], c[1], c[2], c[3],
                             al[mi][0], al[mi][1], al[mi][2], al[mi][3], bh0, bh1);
                    mma16816(c[0], c[1], c[2], c[3],
                             ah[mi][0], ah[mi][1], ah[mi][2], ah[mi][3], bl0, bl1);
                }
            }
        }
    }

    #pragma unroll
    for (int mi = 0; mi < 2; mi++) {
        int row0 = bm + wm * 32 + mi * 16 + g;
        int row1 = row0 + 8;
        #pragma unroll
        for (int ni = 0; ni < 8; ni++) {
            int col = bn + wn * 64 + ni * 8 + q * 2;
            if (col >= Vc) continue;
            float b0 = bias[col], b1 = bias[col + 1];
            const float* c = acc[mi][ni];
            if (row0 < NTB) {
                float2 v = make_float2(c[0] + b0, c[1] + b1);
                *(float2*)&out[(size_t)row0 * Vc + col] = v;
            }
            if (row1 < NTB) {
                float2 v = make_float2(c[2] + b0, c[3] + b1);
                *(float2*)&out[(size_t)row1 * Vc + col] = v;
            }
        }
    }
}

// ---------------- host ----------------
extern "C" void kernel_launch(void* const* d_in, const int* in_sizes, int n_in,
                              void* d_out, int out_size)
{
    const float* img   = (const float*)d_in[0];
    const int*   caps  = (const int*)  d_in[1];
    const float* Wh1   = (const float*)d_in[2];
    const float* bh1   = (const float*)d_in[3];
    const float* Wh2   = (const float*)d_in[4];
    const float* bh2   = (const float*)d_in[5];
    const float* Wc1   = (const float*)d_in[6];
    const float* bc1   = (const float*)d_in[7];
    const float* Wc2   = (const float*)d_in[8];
    const float* bc2   = (const float*)d_in[9];
    const float* emb   = (const float*)d_in[10];
    const float* Wih0f = (const float*)d_in[11];
    const float* Whh0f = (const float*)d_in[12];
    const float* b0f   = (const float*)d_in[13];
    const float* Wih0b = (const float*)d_in[14];
    const float* Whh0b = (const float*)d_in[15];
    const float* b0b   = (const float*)d_in[16];
    const float* Wih1f = (const float*)d_in[17];
    const float* Whh1f = (const float*)d_in[18];
    const float* b1f   = (const float*)d_in[19];
    const float* Wih1b = (const float*)d_in[20];
    const float* Whh1b = (const float*)d_in[21];
    const float* b1b   = (const float*)d_in[22];
    const float* Wfc   = (const float*)d_in[23];
    const float* bfc   = (const float*)d_in[24];
    float* outp = (float*)d_out;

    float *p_W0T, *p_W1T;
    cudaGetSymbolAddress((void**)&p_W0T,  g_W0T);
    cudaGetSymbolAddress((void**)&p_W1T,  g_W1T);

    const size_t W1ROW = (size_t)H4 * (Hc + H2);

    // Launch 0: transposes + MLP stage1 + gather + convB (fused 1-D dispatch)
    TParams6 tp;
    tp.p[0] = { Whh0f, p_W0T,                 Hc, Hc };
    tp.p[1] = { Whh0b, p_W0T + (size_t)H4*Hc, Hc, Hc };
    tp.p[2] = { Whh1f, p_W1T,                 Hc, Hc + H2 };
    tp.p[3] = { Wih1f, p_W1T + Hc,            H2, Hc + H2 };
    tp.p[4] = { Whh1b, p_W1T + W1ROW,         Hc, Hc + H2 };
    tp.p[5] = { Wih1b, p_W1T + W1ROW + Hc,    H2, Hc + H2 };
    pre1<<<P1_TOTAL, 256>>>(tp, img, Wh1, bh1, Wc1, bc1, caps, emb, Wfc);

    // Launch 1: MLP stage2 (dual)
    pre2k<<<dim3(Hc/64, 1, 2), 256>>>(Wh2, bh2, Wc2, bc2);

    // Launch 2: xg0 GEMMs (z=0,1) + k-major state broadcast (z=2)
    pre3<<<dim3(H4/128, (NTB+127)/128, 3), 256>>>(Wih0f, b0f, Wih0b, b0b);

    // Launch 3: persistent recurrent chain (512 threads, 32 k-slices) + fused convA
    cudaFuncSetAttribute(lstm_persist, cudaFuncAttributeMaxDynamicSharedMemorySize, LSTM_SMEM);
    lstm_persist<<<NBLK, 512, LSTM_SMEM>>>(b1f, b1b);

    // Launch 4: tensor-core FC
    cudaFuncSetAttribute(fc_wmma, cudaFuncAttributeMaxDynamicSharedMemorySize, FC_SMEM);
    fc_wmma<<<dim3((Vc + FCBN - 1)/FCBN, (NTB + FCBM - 1)/FCBM), 256, FC_SMEM>>>(bfc, outp);
}

// round 14
// speedup vs baseline: 1.0483x; 1.0483x over previous
#include <cuda_runtime.h>
#include <cuda_bf16.h>
#include <math.h>
#include <stdint.h>

// Problem constants
#define Bc 16
#define Nc 5
#define Tc 10
#define Hc 512
#define Ec 250
#define Vc 30000
#define Fc 2048
#define H4 2048
#define H2 1024
#define NTB (Nc*Tc*Bc)   // 800
#define NBLK 128

// packed fp32x2 FMA (SASS FFMA2)
#define FMA2(d, a, b) asm("fma.rn.f32x2 %0, %1, %2, %0;" : "+l"(d) : "l"(a), "l"(b))

__device__ __forceinline__ float f2lo(unsigned long long v) { return __uint_as_float((unsigned)v); }
__device__ __forceinline__ float f2hi(unsigned long long v) { return __uint_as_float((unsigned)(v >> 32)); }
__device__ __forceinline__ unsigned long long splat2(float w) {
    unsigned long long d;
    asm("mov.b64 %0, {%1, %1};" : "=l"(d) : "r"(__float_as_uint(w)));
    return d;
}

// hs bank-swizzled slot address: (k, q) -> byte offset; q = b-group (4 floats)
__device__ __forceinline__ int hs_off(int k, int q) {
    return (((k) << 6) | ((q) << 4)) ^ ((k & 0x1C) << 2);
}

// ---------------- device scratch ----------------
__device__ __align__(16) float g_tmp[Bc*H2];
__device__ __align__(16) float g_tmp2[Bc*H2];
__device__ __align__(16) float g_h0[Bc*Hc];          // [b][k]
__device__ __align__(16) float g_c0[Bc*Hc];          // [b][k]
__device__ __align__(16) float g_hst[4][2][Hc*Bc];   // state h, k-major [k][b]
__device__ __align__(16) float g_cst[4][Hc*Bc];      // state c, k-major
__device__ __align__(16) float g_x0[NTB*Ec];
__device__ __align__(16) float g_xg0[2*NTB*H4];
__device__ __align__(16) float g_x1[Tc*H2*Bc];       // [t][k][b] k-major
__device__ __align__(16) float g_out1[NTB*H2];
__device__ __align__(16) float g_W0T[2*H4*Hc];
__device__ __align__(16) float g_W1T[2*H4*(Hc+H2)];
__device__ __align__(16) __nv_bfloat16 g_Ahi[NTB*H2];
__device__ __align__(16) __nv_bfloat16 g_Alo[NTB*H2];
__device__ __align__(16) __nv_bfloat16 g_Bhi[(size_t)Vc*H2];
__device__ __align__(16) __nv_bfloat16 g_Blo[(size_t)Vc*H2];

__device__ unsigned g_barcnt = 0;
__device__ unsigned g_barsense = 0;

// ---------------- shared sgemm body (64x64 tiles) ----------------
struct TParam { const float* in; float* out; int R; int ostride; };
struct TParams6 { TParam p[6]; };

__device__ __forceinline__ void sgemm_body(
    const float* A, const float* W, const float* bias, float* C,
    int M, int N, int K, int relu, int bm, int bn, int tid,
    float* As, float* Bs)
{
    int tm = (tid >> 4) << 2;
    int tn = (tid & 15) << 2;
    float acc[4][4] = {};
    for (int k0 = 0; k0 < K; k0 += 16) {
        #pragma unroll
        for (int e = 0; e < 4; e++) {
            int idx = tid + e * 256;
            int r = idx >> 4, c = idx & 15;
            int gr = bm + r, gc = k0 + c;
            As[c * 64 + r] = (gr < M && gc < K) ? A[(size_t)gr * K + gc] : 0.f;
        }
        #pragma unroll
        for (int e = 0; e < 4; e++) {
            int idx = tid + e * 256;
            int r = idx >> 6, c = idx & 63;
            int gr = k0 + r, gc = bn + c;
            Bs[r * 64 + c] = (gr < K && gc < N) ? W[(size_t)gr * N + gc] : 0.f;
        }
        __syncthreads();
        #pragma unroll
        for (int kk = 0; kk < 16; kk++) {
            float4 a4 = *(const float4*)&As[kk * 64 + tm];
            float4 b4 = *(const float4*)&Bs[kk * 64 + tn];
            float a[4] = {a4.x, a4.y, a4.z, a4.w};
            float b[4] = {b4.x, b4.y, b4.z, b4.w};
            #pragma unroll
            for (int i = 0; i < 4; i++)
                #pragma unroll
                for (int j = 0; j < 4; j++)
                    acc[i][j] = fmaf(a[i], b[j], acc[i][j]);
        }
        __syncthreads();
    }
    #pragma unroll
    for (int i = 0; i < 4; i++) {
        int gm = bm + tm + i;
        if (gm >= M) continue;
        #pragma unroll
        for (int j = 0; j < 4; j++) {
            int gn = bn + tn + j;
            if (gn >= N) continue;
            float v = acc[i][j] + bias[gn];
            if (relu) v = fmaxf(v, 0.f);
            C[(size_t)gm * N + gn] = v;
        }
    }
}

// ================= pre1: transposes + MLP stage1 + gather + convB =================
#define P1_TRANS 12288           // 6 * 64 * 32
#define P1_MLP   (P1_TRANS + 32)
#define P1_GATH  (P1_MLP + 800)
#define P1_TOTAL (P1_GATH + 30016)   // 938*32 convB blocks

__global__ __launch_bounds__(256) void pre1(
    TParams6 tp,
    const float* __restrict__ img,
    const float* __restrict__ Wh1, const float* __restrict__ bh1,
    const float* __restrict__ Wc1, const float* __restrict__ bc1,
    const int* __restrict__ caps, const float* __restrict__ emb,
    const float* __restrict__ Wfc)
{
    __shared__ float sh[2048];
    int id = blockIdx.x, tid = threadIdx.x;
    int tx = tid & 31, ty = tid >> 5;

    if (id < P1_TRANS) {
        int which = id / 2048, rem = id % 2048;
        int bx = rem & 63, by = rem >> 6;
        TParam p = tp.p[which];
        int c0 = bx * 32, r0 = by * 32;
        if (r0 >= p.R) return;
        for (int j = ty; j < 32; j += 8) {
            int r = r0 + j, c = c0 + tx;
            sh[j * 33 + tx] = (r < p.R) ? p.in[(size_t)r * H4 + c] : 0.f;
        }
        __syncthreads();
        for (int j = ty; j < 32; j += 8) {
            int c = c0 + j, r = r0 + tx;
            if (r < p.R) p.out[(size_t)c * p.ostride + r] = sh[tx * 33 + j];
        }
    } else if (id < P1_MLP) {
        int sub = id - P1_TRANS;
        int z = sub >> 4, bx = sub & 15;
        sgemm_body(img, z ? Wc1 : Wh1, z ? bc1 : bh1, z ? g_tmp2 : g_tmp,
                   Bc, H2, Fc, 1, 0, bx * 64, tid, sh, sh + 1024);
    } else if (id < P1_GATH) {
        int rid = id - P1_MLP;
        int b = rid & 15;
        int nt = rid >> 4;
        int n = nt / Tc, t = nt % Tc;
        int tok = caps[b * (Nc * Tc) + n * Tc + t];
        const float* e = emb + (size_t)tok * Ec;
        float* o = g_x0 + (size_t)rid * Ec;
        for (int i = tid; i < Ec; i += 256) o[i] = e[i];
    } else {
        int sub = id - P1_GATH;
        int n0 = (sub % 938) * 32, k0 = (sub / 938) * 32;
        for (int j = ty; j < 32; j += 8) {
            int k = k0 + j, n = n0 + tx;
            sh[j * 33 + tx] = (n < Vc) ? Wfc[(size_t)k * Vc + n] : 0.f;
        }
        __syncthreads();
        for (int j = ty; j < 32; j += 8) {
            int n = n0 + j, k = k0 + tx;
            if (n < Vc) {
                float v = sh[tx * 33 + j];
                __nv_bfloat16 h = __float2bfloat16(v);
                g_Bhi[(size_t)n * H2 + k] = h;
                g_Blo[(size_t)n * H2 + k] = __float2bfloat16(v - __bfloat162float(h));
            }
        }
    }
}

// ================= pre2: MLP stage2 (dual via z) =================
__global__ __launch_bounds__(256) void pre2k(
    const float* __restrict__ Wh2, const float* __restrict__ bh2,
    const float* __restrict__ Wc2, const float* __restrict__ bc2)
{
    __shared__ float sh[2048];
    int z = blockIdx.z;
    sgemm_body(z ? g_tmp2 : g_tmp, z ? Wc2 : Wh2, z ? bc2 : bh2, z ? g_c0 : g_h0,
               Bc, Hc, H2, 1, 0, blockIdx.x * 64, threadIdx.x, sh, sh + 1024);
}

// ================= pre3: xg0 GEMM (z=0,1) + state broadcast k-major (z=2) =================
__global__ __launch_bounds__(256) void pre3(
    const float* __restrict__ B0, const float* __restrict__ bias0,
    const float* __restrict__ B1, const float* __restrict__ bias1)
{
    __shared__ __align__(16) float As[2][16][128];
    __shared__ __align__(16) float Bs[2][16][256];

    if (blockIdx.z == 2) {
        int lin = blockIdx.y * 16 + blockIdx.x;
        if (lin < 32) {
            int i = lin * 256 + threadIdx.x;   // i = k*16 + b
            int k = i >> 4, b = i & 15;
            float h = g_h0[b * Hc + k];
            float c = g_c0[b * Hc + k];
            #pragma unroll
            for (int s = 0; s < 4; s++) {
                g_hst[s][0][i] = h;
                g_cst[s][i]    = c;
            }
        }
        return;
    }

    const float* A = g_x0;
    const float* B = blockIdx.z ? B1 : B0;
    const float* bias = blockIdx.z ? bias1 : bias0;
    float* C = blockIdx.z ? (g_xg0 + (size_t)NTB * H4) : g_xg0;
    const int M = NTB, N = H4, K = Ec;

    int tid = threadIdx.x;
    int bm = blockIdx.y * 128, bn = blockIdx.x * 128;
    int tx = tid & 15, ty = tid >> 4;
    int ar = tid >> 2, ac = (tid & 3) * 4;
    int br = tid >> 5, bc = (tid & 31) * 4;

    unsigned long long acc[4][8];
    #pragma unroll
    for (int i = 0; i < 4; i++)
        #pragma unroll
        for (int j = 0; j < 8; j++) acc[i][j] = 0ull;

    float a0[4], a1[4], b0[4], b1[4];
    int KT = (K + 15) / 16;

#define LOADTILE(KT_) do {                                                        \
    int k0 = (KT_) * 16;                                                          \
    int gr0 = bm + ar, gr1 = bm + ar + 64;                                        \
    _Pragma("unroll") for (int j = 0; j < 4; j++) {                               \
        int gk = k0 + ac + j;                                                     \
        bool ok = (gk < K);                                                       \
        a0[j] = (ok && gr0 < M) ? A[(size_t)gr0 * K + gk] : 0.f;                  \
        a1[j] = (ok && gr1 < M) ? A[(size_t)gr1 * K + gk] : 0.f;                  \
    }                                                                             \
    int gk0 = k0 + br, gk1 = k0 + br + 8;                                         \
    _Pragma("unroll") for (int j = 0; j < 4; j++) {                               \
        int gc = bn + bc + j;                                                     \
        b0[j] = (gk0 < K) ? B[(size_t)gk0 * N + gc] : 0.f;                        \
        b1[j] = (gk1 < K) ? B[(size_t)gk1 * N + gc] : 0.f;                        \
    }                                                                             \
} while (0)

#define STORETILE(BUF_) do {                                                      \
    _Pragma("unroll") for (int j = 0; j < 4; j++) {                               \
        As[BUF_][ac + j][ar]      = a0[j];                                        \
        As[BUF_][ac + j][ar + 64] = a1[j];                                        \
        Bs[BUF_][br][(bc + j) * 2]         = b0[j];                               \
        Bs[BUF_][br][(bc + j) * 2 + 1]     = b0[j];                               \
        Bs[BUF_][br + 8][(bc + j) * 2]     = b1[j];                               \
        Bs[BUF_][br + 8][(bc + j) * 2 + 1] = b1[j];                               \
    }                                                                             \
} while (0)

    LOADTILE(0);
    STORETILE(0);
    __syncthreads();

    for (int kt = 0; kt < KT; kt++) {
        int cur = kt & 1;
        if (kt + 1 < KT) LOADTILE(kt + 1);
        #pragma unroll
        for (int k = 0; k < 16; k++) {
            unsigned long long a2[4], b2[8];
            #pragma unroll
            for (int i = 0; i < 4; i++)
                a2[i] = *(const unsigned long long*)&As[cur][k][ty * 8 + 2 * i];
            #pragma unroll
            for (int j = 0; j < 8; j++)
                b2[j] = *(const unsigned long long*)&Bs[cur][k][(tx + 16 * j) * 2];
            #pragma unroll
            for (int i = 0; i < 4; i++)
                #pragma unroll
                for (int j = 0; j < 8; j++)
                    FMA2(acc[i][j], a2[i], b2[j]);
        }
        if (kt + 1 < KT) STORETILE(cur ^ 1);
        __syncthreads();
    }

    #pragma unroll
    for (int j = 0; j < 8; j++) {
        int col = bn + tx + 16 * j;
        float bb = bias[col];
        #pragma unroll
        for (int i = 0; i < 4; i++) {
            int r0 = bm + ty * 8 + 2 * i;
            float lo = f2lo(acc[i][j]) + bb;
            float hi = f2hi(acc[i][j]) + bb;
            if (r0 < M)     C[(size_t)r0 * N + col] = lo;
            if (r0 + 1 < M) C[(size_t)(r0 + 1) * N + col] = hi;
        }
    }
#undef LOADTILE
#undef STORETILE
}

// ================= persistent recurrent kernel (R12 proven config) =================
__device__ __forceinline__ void grid_bar(unsigned& sense)
{
    __syncthreads();
    sense ^= 1;
    if (threadIdx.x == 0) {
        __threadfence();
        unsigned old = atomicAdd(&g_barcnt, 1);
        if (old == NBLK - 1) {
            g_barcnt = 0;
            __threadfence();
            atomicExch(&g_barsense, sense);
        } else {
            while (*(volatile unsigned*)&g_barsense != sense) __nanosleep(32);
        }
        __threadfence();
    }
    __syncthreads();
}

// red layout: row (0..31) stride 1280 B; ksub (0..15) stride 80 B; b (0..15) * 4 B
#define RED_ROWSTRIDE 1280
#define RED_BYTES (32 * RED_ROWSTRIDE)     // 40960

template<int LAYER>
__device__ __forceinline__ void lstm_do_step(
    int tid, int dir, int bkid, int ksub, int bs, int rg,
    char* hsb, char* redb,
    int n, int tok, int par,
    const float* bias1, const float* xg0d, unsigned& sense)
{
    const int K = LAYER ? (Hc + H2) : Hc;
    int slot = LAYER ? (2 + dir) : dir;
    const float* hglob = &g_hst[slot][par][0];
    float* hout = &g_hst[slot][par ^ 1][0];
    float* cst  = &g_cst[slot][0];
    const float* WT = LAYER ? (g_W1T + (size_t)dir * H4 * (Hc + H2))
                            : (g_W0T + (size_t)dir * H4 * Hc);

    // stage A: stage h (and x1 for layer1) into bank-swizzled smem
    {
        const float* x1g = g_x1 + (size_t)tok * H2 * Bc;
        int nf4 = K * 4;
        for (int idx = tid; idx < nf4; idx += 256) {
            int k = idx >> 2, q = idx & 3;
            float4 v;
            if (!LAYER || k < Hc) v = *(const float4*)&hglob[k * Bc + q * 4];
            else                  v = *(const float4*)&x1g[(size_t)(k - Hc) * Bc + q * 4];
            *(float4*)(hsb + hs_off(k, q)) = v;
        }
    }
    __syncthreads();

    // stage B: 8 rows per thread (consecutive m), 16 k-slices, double-buffered weights
    const float4* pw = (const float4*)(WT + (size_t)(rg * Hc + bkid * 8) * K);
    const int RS = K / 4;            // f4 row stride
    const int KI = K / 64;           // chunks (8 or 24)

    unsigned long long acc0[8], acc1[8];
    #pragma unroll
    for (int j = 0; j < 8; j++) { acc0[j] = 0ull; acc1[j] = 0ull; }

    float4 cur[8], nxt[8];
    #pragma unroll
    for (int j = 0; j < 8; j++) cur[j] = pw[j * RS + ksub];

    #pragma unroll 2
    for (int i = 0; i < KI; i++) {
        int nf = ((i + 1 < KI) ? (i + 1) : i) * 16 + ksub;
        #pragma unroll
        for (int j = 0; j < 8; j++) nxt[j] = pw[j * RS + nf];
        int kb = i * 64 + ksub * 4;
        #pragma unroll
        for (int kk = 0; kk < 4; kk++) {
            ulonglong2 hv = *(const ulonglong2*)(hsb + hs_off(kb + kk, bs));
            #pragma unroll
            for (int j = 0; j < 8; j++) {
                unsigned long long s = splat2(((const float*)&cur[j])[kk]);
                FMA2(acc0[j], s, hv.x);
                FMA2(acc1[j], s, hv.y);
            }
        }
        #pragma unroll
        for (int j = 0; j < 8; j++) cur[j] = nxt[j];
    }

    // stage C: dump partials; acc0 = (b0,b1), acc1 = (b2,b3) for each row
    #pragma unroll
    for (int j = 0; j < 8; j++) {
        int row = rg * 8 + j;
        float4 v = make_float4(f2lo(acc0[j]), f2hi(acc0[j]),
                               f2lo(acc1[j]), f2hi(acc1[j]));
        *(float4*)(redb + row * RED_ROWSTRIDE + ksub * 80 + bs * 16) = v;
    }
    __syncthreads();

    // stage D: reduce over 16 ksub + nonlinearity + state update
    if (tid < 128) {
        int ko_l = tid & 7, b = tid >> 3;
        int ko = bkid * 8 + ko_l;
        float gsum[4];
        #pragma unroll
        for (int g = 0; g < 4; g++) {
            int row = g * 8 + ko_l;
            const char* base = redb + row * RED_ROWSTRIDE;
            float ss = 0.f;
            #pragma unroll
            for (int ks = 0; ks < 16; ks++)
                ss += ((const float*)(base + ks * 80))[b];
            gsum[g] = ss;
        }
        float pi, pf, pg, po;
        if (LAYER) {
            pi = bias1[ko]; pf = bias1[512 + ko];
            pg = bias1[1024 + ko]; po = bias1[1536 + ko];
        } else {
            const float* xg = xg0d + ((size_t)(n * Tc + tok) * Bc + b) * H4 + ko;
            pi = xg[0]; pf = xg[512]; pg = xg[1024]; po = xg[1536];
        }
        float gi = gsum[0] + pi, gf = gsum[1] + pf, gg = gsum[2] + pg, go = gsum[3] + po;
        float si = 1.f / (1.f + expf(-gi));
        float sf = 1.f / (1.f + expf(-gf));
        float so = 1.f / (1.f + expf(-go));
        int idx = ko * Bc + b;
        float cn = sf * cst[idx] + si * tanhf(gg);
        float hn = so * tanhf(cn);
        cst[idx]  = cn;
        hout[idx] = hn;
        if (LAYER) {
            g_out1[((size_t)(n * Tc + tok) * Bc + b) * H2 + dir * Hc + ko] = hn;
        } else {
            g_x1[((size_t)tok * H2 + dir * Hc + ko) * Bc + b] = hn;
        }
    }
    grid_bar(sense);
}

#define HS_BYTES ((Hc + H2) * 64)          // 98304
#define LSTM_SMEM (HS_BYTES + RED_BYTES)   // 139264

__global__ __launch_bounds__(256, 1) void lstm_persist(
    const float* __restrict__ b1f_, const float* __restrict__ b1b_)
{
    extern __shared__ __align__(16) char smemc[];
    char* hsb  = smemc;
    char* redb = smemc + HS_BYTES;

    int tid = threadIdx.x, bid = blockIdx.x;
    int dir = bid >> 6, bkid = bid & 63;
    // warp-friendly mapping: all 4 bs duplicates in-warp, ksub_h = bit 5
    int ksub = (tid & 7) | (((tid >> 5) & 1) << 3);
    int bs   = (tid >> 3) & 3;
    int rg   = tid >> 6;

    const float* bias1 = dir ? b1b_ : b1f_;
    const float* xg0d  = g_xg0 + (size_t)dir * NTB * H4;

    unsigned sense = 0;
    int p0 = 0, p1 = 0;

    for (int t = 0; t < Tc; t++) {
        for (int n = 0; n < Nc; n++) {
            int L = t + 1;
            for (int s = 0; s < L; s++) {
                int tok = dir ? (L - 1 - s) : s;
                lstm_do_step<0>(tid, dir, bkid, ksub, bs, rg, hsb, redb,
                                n, tok, p0, bias1, xg0d, sense);
                p0 ^= 1;
            }
            for (int s = 0; s < L; s++) {
                int tok = dir ? (L - 1 - s) : s;
                lstm_do_step<1>(tid, dir, bkid, ksub, bs, rg, hsb, redb,
                                n, tok, p1, bias1, xg0d, sense);
                p1 ^= 1;
            }
        }
    }

    // fused convA: out1 -> bf16 hi/lo (all out1 writes visible after final grid_bar)
    for (int i = bid * 256 + tid; i < NTB * H2; i += NBLK * 256) {
        float v = g_out1[i];
        __nv_bfloat16 h = __float2bfloat16(v);
        g_Ahi[i] = h;
        g_Alo[i] = __float2bfloat16(v - __bfloat162float(h));
    }
}

// ================= bf16-split mma.sync FC =================
#define FCBM 128
#define FCBN 128
#define FCBK 64
#define PADK 72
#define FC_SMEM (4 * FCBM * PADK * 2)

__device__ __forceinline__ void mma16816(
    float& c0, float& c1, float& c2, float& c3,
    uint32_t a0, uint32_t a1, uint32_t a2, uint32_t a3,
    uint32_t b0, uint32_t b1)
{
    asm volatile(
        "mma.sync.aligned.m16n8k16.row.col.f32.bf16.bf16.f32 "
        "{%0,%1,%2,%3}, {%4,%5,%6,%7}, {%8,%9}, {%0,%1,%2,%3};"
        : "+f"(c0), "+f"(c1), "+f"(c2), "+f"(c3)
        : "r"(a0), "r"(a1), "r"(a2), "r"(a3), "r"(b0), "r"(b1));
}

__global__ __launch_bounds__(256) void fc_wmma(
    const float* __restrict__ bias, float* __restrict__ out)
{
    extern __shared__ __align__(16) __nv_bfloat16 sm[];
    __nv_bfloat16* sAh = sm;
    __nv_bfloat16* sAl = sm + FCBM * PADK;
    __nv_bfloat16* sBh = sm + 2 * FCBM * PADK;
    __nv_bfloat16* sBl = sm + 3 * FCBM * PADK;

    int tid = threadIdx.x;
    int wid = tid >> 5, lane = tid & 31;
    int g = lane >> 2, q = lane & 3;
    int wm = wid & 3, wn = wid >> 2;
    int bm = blockIdx.y * FCBM, bn = blockIdx.x * FCBN;

    const uint4* A4h = (const uint4*)g_Ahi;
    const uint4* A4l = (const uint4*)g_Alo;
    const uint4* B4h = (const uint4*)g_Bhi;
    const uint4* B4l = (const uint4*)g_Blo;
    const uint4 z4 = make_uint4(0, 0, 0, 0);

    float acc[2][8][4];
    #pragma unroll
    for (int i = 0; i < 2; i++)
        #pragma unroll
        for (int j = 0; j < 8; j++)
            #pragma unroll
            for (int e = 0; e < 4; e++) acc[i][j][e] = 0.f;

    const uint32_t* sA32h = (const uint32_t*)sAh;
    const uint32_t* sA32l = (const uint32_t*)sAl;
    const uint32_t* sB32h = (const uint32_t*)sBh;
    const uint32_t* sB32l = (const uint32_t*)sBl;

    for (int kc = 0; kc < H2 / FCBK; kc++) {
        __syncthreads();
        #pragma unroll
        for (int it = 0; it < 4; it++) {
            int idx = tid + it * 256;
            int m = idx >> 3, kg = idx & 7;
            int gm = bm + m;
            size_t gi = (size_t)gm * (H2 / 8) + kc * 8 + kg;
            uint4 vh = z4, vl = z4;
            if (gm < NTB) { vh = A4h[gi]; vl = A4l[gi]; }
            *(uint4*)&sAh[m * PADK + kg * 8] = vh;
            *(uint4*)&sAl[m * PADK + kg * 8] = vl;
        }
        #pragma unroll
        for (int it = 0; it < 4; it++) {
            int idx = tid + it * 256;
            int n = idx >> 3, kg = idx & 7;
            int gn = bn + n;
            uint4 vh = z4, vl = z4;
            if (gn < Vc) {
                size_t gi = (size_t)gn * (H2 / 8) + kc * 8 + kg;
                vh = B4h[gi]; vl = B4l[gi];
            }
            *(uint4*)&sBh[n * PADK + kg * 8] = vh;
            *(uint4*)&sBl[n * PADK + kg * 8] = vl;
        }
        __syncthreads();

        #pragma unroll
        for (int ks = 0; ks < 4; ks++) {
            uint32_t ah[2][4], al[2][4];
            #pragma unroll
            for (int mi = 0; mi < 2; mi++) {
                int r0 = (wm * 32 + mi * 16 + g) * (PADK / 2);
                int r8 = r0 + 8 * (PADK / 2);
                int w0 = ks * 8 + q, w4 = w0 + 4;
                ah[mi][0] = sA32h[r0 + w0]; ah[mi][1] = sA32h[r8 + w0];
                ah[mi][2] = sA32h[r0 + w4]; ah[mi][3] = sA32h[r8 + w4];
                al[mi][0] = sA32l[r0 + w0]; al[mi][1] = sA32l[r8 + w0];
                al[mi][2] = sA32l[r0 + w4]; al[mi][3] = sA32l[r8 + w4];
            }
            #pragma unroll
            for (int ni = 0; ni < 8; ni++) {
                int nr = (wn * 64 + ni * 8 + g) * (PADK / 2);
                int w0 = ks * 8 + q, w4 = w0 + 4;
                uint32_t bh0 = sB32h[nr + w0], bh1 = sB32h[nr + w4];
                uint32_t bl0 = sB32l[nr + w0], bl1 = sB32l[nr + w4];
                #pragma unroll
                for (int mi = 0; mi < 2; mi++) {
                    float* c = acc[mi][ni];
                    mma16816(c[0], c[1], c[2], c[3],
                             ah[mi][0], ah[mi][1], ah[mi][2], ah[mi][3], bh0, bh1);
                    mma16816(c[0], c[1], c[2], c[3],
                             al[mi][0], al[mi][1], al[mi][2], al[mi][3], bh0, bh1);
                    mma16816(c[0], c[1], c[2], c[3],
                             ah[mi][0], ah[mi][1], ah[mi][2], ah[mi][3], bl0, bl1);
                }
            }
        }
    }

    #pragma unroll
    for (int mi = 0; mi < 2; mi++) {
        int row0 = bm + wm * 32 + mi * 16 + g;
        int row1 = row0 + 8;
        #pragma unroll
        for (int ni = 0; ni < 8; ni++) {
            int col = bn + wn * 64 + ni * 8 + q * 2;
            if (col >= Vc) continue;
            float b0 = bias[col], b1 = bias[col + 1];
            const float* c = acc[mi][ni];
            if (row0 < NTB) {
                float2 v = make_float2(c[0] + b0, c[1] + b1);
                *(float2*)&out[(size_t)row0 * Vc + col] = v;
            }
            if (row1 < NTB) {
                float2 v = make_float2(c[2] + b0, c[3] + b1);
                *(float2*)&out[(size_t)row1 * Vc + col] = v;
            }
        }
    }
}

// ---------------- host ----------------
extern "C" void kernel_launch(void* const* d_in, const int* in_sizes, int n_in,
                              void* d_out, int out_size)
{
    const float* img   = (const float*)d_in[0];
    const int*   caps  = (const int*)  d_in[1];
    const float* Wh1   = (const float*)d_in[2];
    const float* bh1   = (const float*)d_in[3];
    const float* Wh2   = (const float*)d_in[4];
    const float* bh2   = (const float*)d_in[5];
    const float* Wc1   = (const float*)d_in[6];
    const float* bc1   = (const float*)d_in[7];
    const float* Wc2   = (const float*)d_in[8];
    const float* bc2   = (const float*)d_in[9];
    const float* emb   = (const float*)d_in[10];
    const float* Wih0f = (const float*)d_in[11];
    const float* Whh0f = (const float*)d_in[12];
    const float* b0f   = (const float*)d_in[13];
    const float* Wih0b = (const float*)d_in[14];
    const float* Whh0b = (const float*)d_in[15];
    const float* b0b   = (const float*)d_in[16];
    const float* Wih1f = (const float*)d_in[17];
    const float* Whh1f = (const float*)d_in[18];
    const float* b1f   = (const float*)d_in[19];
    const float* Wih1b = (const float*)d_in[20];
    const float* Whh1b = (const float*)d_in[21];
    const float* b1b   = (const float*)d_in[22];
    const float* Wfc   = (const float*)d_in[23];
    const float* bfc   = (const float*)d_in[24];
    float* outp = (float*)d_out;

    float *p_W0T, *p_W1T;
    cudaGetSymbolAddress((void**)&p_W0T,  g_W0T);
    cudaGetSymbolAddress((void**)&p_W1T,  g_W1T);

    const size_t W1ROW = (size_t)H4 * (Hc + H2);

    // Launch 0: transposes + MLP stage1 + gather + convB (fused 1-D dispatch)
    TParams6 tp;
    tp.p[0] = { Whh0f, p_W0T,                 Hc, Hc };
    tp.p[1] = { Whh0b, p_W0T + (size_t)H4*Hc, Hc, Hc };
    tp.p[2] = { Whh1f, p_W1T,                 Hc, Hc + H2 };
    tp.p[3] = { Wih1f, p_W1T + Hc,            H2, Hc + H2 };
    tp.p[4] = { Whh1b, p_W1T + W1ROW,         Hc, Hc + H2 };
    tp.p[5] = { Wih1b, p_W1T + W1ROW + Hc,    H2, Hc + H2 };
    pre1<<<P1_TOTAL, 256>>>(tp, img, Wh1, bh1, Wc1, bc1, caps, emb, Wfc);

    // Launch 1: MLP stage2 (dual)
    pre2k<<<dim3(Hc/64, 1, 2), 256>>>(Wh2, bh2, Wc2, bc2);

    // Launch 2: xg0 GEMMs (z=0,1) + k-major state broadcast (z=2)
    pre3<<<dim3(H4/128, (NTB+127)/128, 3), 256>>>(Wih0f, b0f, Wih0b, b0b);

    // Launch 3: persistent recurrent chain (R12 config) + fused convA
    cudaFuncSetAttribute(lstm_persist, cudaFuncAttributeMaxDynamicSharedMemorySize, LSTM_SMEM);
    lstm_persist<<<NBLK, 256, LSTM_SMEM>>>(b1f, b1b);

    // Launch 4: tensor-core FC
    cudaFuncSetAttribute(fc_wmma, cudaFuncAttributeMaxDynamicSharedMemorySize, FC_SMEM);
    fc_wmma<<<dim3((Vc + FCBN - 1)/FCBN, (NTB + FCBM - 1)/FCBM), 256, FC_SMEM>>>(bfc, outp);
}

// round 15
// speedup vs baseline: 1.0571x; 1.0084x over previous
#include <cuda_runtime.h>
#include <cuda_bf16.h>
#include <math.h>
#include <stdint.h>

// Problem constants
#define Bc 16
#define Nc 5
#define Tc 10
#define Hc 512
#define Ec 250
#define Vc 30000
#define Fc 2048
#define H4 2048
#define H2 1024
#define NTB (Nc*Tc*Bc)   // 800
#define NBLK 128

// packed fp32x2 FMA (SASS FFMA2)
#define FMA2(d, a, b) asm("fma.rn.f32x2 %0, %1, %2, %0;" : "+l"(d) : "l"(a), "l"(b))

__device__ __forceinline__ float f2lo(unsigned long long v) { return __uint_as_float((unsigned)v); }
__device__ __forceinline__ float f2hi(unsigned long long v) { return __uint_as_float((unsigned)(v >> 32)); }
__device__ __forceinline__ unsigned long long splat2(float w) {
    unsigned long long d;
    asm("mov.b64 %0, {%1, %1};" : "=l"(d) : "r"(__float_as_uint(w)));
    return d;
}

// hs bank-swizzled slot address: (k, q) -> byte offset; q = b-group (4 floats)
__device__ __forceinline__ int hs_off(int k, int q) {
    return (((k) << 6) | ((q) << 4)) ^ ((k & 0x1C) << 2);
}

// ---------------- device scratch ----------------
__device__ __align__(16) float g_tmp[Bc*H2];
__device__ __align__(16) float g_tmp2[Bc*H2];
__device__ __align__(16) float g_h0[Bc*Hc];          // [b][k]
__device__ __align__(16) float g_c0[Bc*Hc];          // [b][k]
__device__ __align__(16) float g_hst[4][2][Hc*Bc];   // state h, k-major [k][b]
__device__ __align__(16) float g_cst[4][Hc*Bc];      // state c, k-major
__device__ __align__(16) float g_x0[NTB*Ec];
__device__ __align__(16) float g_xg0[2*NTB*H4];
__device__ __align__(16) float g_x1[Tc*H2*Bc];       // [t][k][b] k-major
__device__ __align__(16) float g_out1[NTB*H2];
__device__ __align__(16) float g_W0T[2*H4*Hc];
__device__ __align__(16) float g_W1T[2*H4*(Hc+H2)];
__device__ __align__(16) __nv_bfloat16 g_Ahi[NTB*H2];
__device__ __align__(16) __nv_bfloat16 g_Alo[NTB*H2];
__device__ __align__(16) __nv_bfloat16 g_Bhi[(size_t)Vc*H2];
__device__ __align__(16) __nv_bfloat16 g_Blo[(size_t)Vc*H2];

// barrier state: slot 0 = dir0 (64 blocks), slot 1 = dir1 (64), slot 2 = full (128)
__device__ __align__(128) unsigned g_cnt[96];   // slot*32, 128B apart
__device__ __align__(128) unsigned g_sns[96];

// ---------------- shared sgemm body (64x64 tiles) ----------------
struct TParam { const float* in; float* out; int R; int ostride; };
struct TParams6 { TParam p[6]; };

__device__ __forceinline__ void sgemm_body(
    const float* A, const float* W, const float* bias, float* C,
    int M, int N, int K, int relu, int bm, int bn, int tid,
    float* As, float* Bs)
{
    int tm = (tid >> 4) << 2;
    int tn = (tid & 15) << 2;
    float acc[4][4] = {};
    for (int k0 = 0; k0 < K; k0 += 16) {
        #pragma unroll
        for (int e = 0; e < 4; e++) {
            int idx = tid + e * 256;
            int r = idx >> 4, c = idx & 15;
            int gr = bm + r, gc = k0 + c;
            As[c * 64 + r] = (gr < M && gc < K) ? A[(size_t)gr * K + gc] : 0.f;
        }
        #pragma unroll
        for (int e = 0; e < 4; e++) {
            int idx = tid + e * 256;
            int r = idx >> 6, c = idx & 63;
            int gr = k0 + r, gc = bn + c;
            Bs[r * 64 + c] = (gr < K && gc < N) ? W[(size_t)gr * N + gc] : 0.f;
        }
        __syncthreads();
        #pragma unroll
        for (int kk = 0; kk < 16; kk++) {
            float4 a4 = *(const float4*)&As[kk * 64 + tm];
            float4 b4 = *(const float4*)&Bs[kk * 64 + tn];
            float a[4] = {a4.x, a4.y, a4.z, a4.w};
            float b[4] = {b4.x, b4.y, b4.z, b4.w};
            #pragma unroll
            for (int i = 0; i < 4; i++)
                #pragma unroll
                for (int j = 0; j < 4; j++)
                    acc[i][j] = fmaf(a[i], b[j], acc[i][j]);
        }
        __syncthreads();
    }
    #pragma unroll
    for (int i = 0; i < 4; i++) {
        int gm = bm + tm + i;
        if (gm >= M) continue;
        #pragma unroll
        for (int j = 0; j < 4; j++) {
            int gn = bn + tn + j;
            if (gn >= N) continue;
            float v = acc[i][j] + bias[gn];
            if (relu) v = fmaxf(v, 0.f);
            C[(size_t)gm * N + gn] = v;
        }
    }
}

// ================= pre1: transposes + MLP stage1 + gather + convB =================
#define P1_TRANS 12288           // 6 * 64 * 32
#define P1_MLP   (P1_TRANS + 32)
#define P1_GATH  (P1_MLP + 800)
#define P1_TOTAL (P1_GATH + 30016)   // 938*32 convB blocks

__global__ __launch_bounds__(256) void pre1(
    TParams6 tp,
    const float* __restrict__ img,
    const float* __restrict__ Wh1, const float* __restrict__ bh1,
    const float* __restrict__ Wc1, const float* __restrict__ bc1,
    const int* __restrict__ caps, const float* __restrict__ emb,
    const float* __restrict__ Wfc)
{
    __shared__ float sh[2048];
    int id = blockIdx.x, tid = threadIdx.x;
    int tx = tid & 31, ty = tid >> 5;

    if (id < P1_TRANS) {
        int which = id / 2048, rem = id % 2048;
        int bx = rem & 63, by = rem >> 6;
        TParam p = tp.p[which];
        int c0 = bx * 32, r0 = by * 32;
        if (r0 >= p.R) return;
        for (int j = ty; j < 32; j += 8) {
            int r = r0 + j, c = c0 + tx;
            sh[j * 33 + tx] = (r < p.R) ? p.in[(size_t)r * H4 + c] : 0.f;
        }
        __syncthreads();
        for (int j = ty; j < 32; j += 8) {
            int c = c0 + j, r = r0 + tx;
            if (r < p.R) p.out[(size_t)c * p.ostride + r] = sh[tx * 33 + j];
        }
    } else if (id < P1_MLP) {
        int sub = id - P1_TRANS;
        int z = sub >> 4, bx = sub & 15;
        sgemm_body(img, z ? Wc1 : Wh1, z ? bc1 : bh1, z ? g_tmp2 : g_tmp,
                   Bc, H2, Fc, 1, 0, bx * 64, tid, sh, sh + 1024);
    } else if (id < P1_GATH) {
        int rid = id - P1_MLP;
        int b = rid & 15;
        int nt = rid >> 4;
        int n = nt / Tc, t = nt % Tc;
        int tok = caps[b * (Nc * Tc) + n * Tc + t];
        const float* e = emb + (size_t)tok * Ec;
        float* o = g_x0 + (size_t)rid * Ec;
        for (int i = tid; i < Ec; i += 256) o[i] = e[i];
    } else {
        int sub = id - P1_GATH;
        int n0 = (sub % 938) * 32, k0 = (sub / 938) * 32;
        for (int j = ty; j < 32; j += 8) {
            int k = k0 + j, n = n0 + tx;
            sh[j * 33 + tx] = (n < Vc) ? Wfc[(size_t)k * Vc + n] : 0.f;
        }
        __syncthreads();
        for (int j = ty; j < 32; j += 8) {
            int n = n0 + j, k = k0 + tx;
            if (n < Vc) {
                float v = sh[tx * 33 + j];
                __nv_bfloat16 h = __float2bfloat16(v);
                g_Bhi[(size_t)n * H2 + k] = h;
                g_Blo[(size_t)n * H2 + k] = __float2bfloat16(v - __bfloat162float(h));
            }
        }
    }
}

// ================= pre2: MLP stage2 (dual via z) =================
__global__ __launch_bounds__(256) void pre2k(
    const float* __restrict__ Wh2, const float* __restrict__ bh2,
    const float* __restrict__ Wc2, const float* __restrict__ bc2)
{
    __shared__ float sh[2048];
    int z = blockIdx.z;
    sgemm_body(z ? g_tmp2 : g_tmp, z ? Wc2 : Wh2, z ? bc2 : bh2, z ? g_c0 : g_h0,
               Bc, Hc, H2, 1, 0, blockIdx.x * 64, threadIdx.x, sh, sh + 1024);
}

// ================= pre3: xg0 GEMM (z=0,1) + state broadcast k-major (z=2) =================
__global__ __launch_bounds__(256) void pre3(
    const float* __restrict__ B0, const float* __restrict__ bias0,
    const float* __restrict__ B1, const float* __restrict__ bias1)
{
    __shared__ __align__(16) float As[2][16][128];
    __shared__ __align__(16) float Bs[2][16][256];

    if (blockIdx.z == 2) {
        int lin = blockIdx.y * 16 + blockIdx.x;
        if (lin < 32) {
            int i = lin * 256 + threadIdx.x;   // i = k*16 + b
            int k = i >> 4, b = i & 15;
            float h = g_h0[b * Hc + k];
            float c = g_c0[b * Hc + k];
            #pragma unroll
            for (int s = 0; s < 4; s++) {
                g_hst[s][0][i] = h;
                g_cst[s][i]    = c;
            }
        }
        return;
    }

    const float* A = g_x0;
    const float* B = blockIdx.z ? B1 : B0;
    const float* bias = blockIdx.z ? bias1 : bias0;
    float* C = blockIdx.z ? (g_xg0 + (size_t)NTB * H4) : g_xg0;
    const int M = NTB, N = H4, K = Ec;

    int tid = threadIdx.x;
    int bm = blockIdx.y * 128, bn = blockIdx.x * 128;
    int tx = tid & 15, ty = tid >> 4;
    int ar = tid >> 2, ac = (tid & 3) * 4;
    int br = tid >> 5, bc = (tid & 31) * 4;

    unsigned long long acc[4][8];
    #pragma unroll
    for (int i = 0; i < 4; i++)
        #pragma unroll
        for (int j = 0; j < 8; j++) acc[i][j] = 0ull;

    float a0[4], a1[4], b0[4], b1[4];
    int KT = (K + 15) / 16;

#define LOADTILE(KT_) do {                                                        \
    int k0 = (KT_) * 16;                                                          \
    int gr0 = bm + ar, gr1 = bm + ar + 64;                                        \
    _Pragma("unroll") for (int j = 0; j < 4; j++) {                               \
        int gk = k0 + ac + j;                                                     \
        bool ok = (gk < K);                                                       \
        a0[j] = (ok && gr0 < M) ? A[(size_t)gr0 * K + gk] : 0.f;                  \
        a1[j] = (ok && gr1 < M) ? A[(size_t)gr1 * K + gk] : 0.f;                  \
    }                                                                             \
    int gk0 = k0 + br, gk1 = k0 + br + 8;                                         \
    _Pragma("unroll") for (int j = 0; j < 4; j++) {                               \
        int gc = bn + bc + j;                                                     \
        b0[j] = (gk0 < K) ? B[(size_t)gk0 * N + gc] : 0.f;                        \
        b1[j] = (gk1 < K) ? B[(size_t)gk1 * N + gc] : 0.f;                        \
    }                                                                             \
} while (0)

#define STORETILE(BUF_) do {                                                      \
    _Pragma("unroll") for (int j = 0; j < 4; j++) {                               \
        As[BUF_][ac + j][ar]      = a0[j];                                        \
        As[BUF_][ac + j][ar + 64] = a1[j];                                        \
        Bs[BUF_][br][(bc + j) * 2]         = b0[j];                               \
        Bs[BUF_][br][(bc + j) * 2 + 1]     = b0[j];                               \
        Bs[BUF_][br + 8][(bc + j) * 2]     = b1[j];                               \
        Bs[BUF_][br + 8][(bc + j) * 2 + 1] = b1[j];                               \
    }                                                                             \
} while (0)

    LOADTILE(0);
    STORETILE(0);
    __syncthreads();

    for (int kt = 0; kt < KT; kt++) {
        int cur = kt & 1;
        if (kt + 1 < KT) LOADTILE(kt + 1);
        #pragma unroll
        for (int k = 0; k < 16; k++) {
            unsigned long long a2[4], b2[8];
            #pragma unroll
            for (int i = 0; i < 4; i++)
                a2[i] = *(const unsigned long long*)&As[cur][k][ty * 8 + 2 * i];
            #pragma unroll
            for (int j = 0; j < 8; j++)
                b2[j] = *(const unsigned long long*)&Bs[cur][k][(tx + 16 * j) * 2];
            #pragma unroll
            for (int i = 0; i < 4; i++)
                #pragma unroll
                for (int j = 0; j < 8; j++)
                    FMA2(acc[i][j], a2[i], b2[j]);
        }
        if (kt + 1 < KT) STORETILE(cur ^ 1);
        __syncthreads();
    }

    #pragma unroll
    for (int j = 0; j < 8; j++) {
        int col = bn + tx + 16 * j;
        float bb = bias[col];
        #pragma unroll
        for (int i = 0; i < 4; i++) {
            int r0 = bm + ty * 8 + 2 * i;
            float lo = f2lo(acc[i][j]) + bb;
            float hi = f2hi(acc[i][j]) + bb;
            if (r0 < M)     C[(size_t)r0 * N + col] = lo;
            if (r0 + 1 < M) C[(size_t)(r0 + 1) * N + col] = hi;
        }
    }
#undef LOADTILE
#undef STORETILE
}

// ================= persistent recurrent kernel =================
// slot-parametrized grid barrier (0/1 = per-dir 64 blocks, 2 = full 128)
__device__ __forceinline__ void gbar(int slot, unsigned nb, unsigned& sense)
{
    __syncthreads();
    sense ^= 1;
    if (threadIdx.x == 0) {
        unsigned* c = &g_cnt[slot * 32];
        unsigned* s = &g_sns[slot * 32];
        __threadfence();
        unsigned old = atomicAdd(c, 1);
        if (old == nb - 1) {
            *c = 0;
            __threadfence();
            atomicExch(s, sense);
        } else {
            while (*(volatile unsigned*)s != sense) __nanosleep(32);
        }
        __threadfence();
    }
    __syncthreads();
}

// red layout: row (0..31) stride 1280 B; ksub (0..15) stride 80 B; b (0..15) * 4 B
#define RED_ROWSTRIDE 1280
#define RED_BYTES (32 * RED_ROWSTRIDE)     // 40960

template<int LAYER>
__device__ __forceinline__ void lstm_do_step(
    int tid, int dir, int bkid, int ksub, int bs, int rg,
    char* hsb, char* redb,
    int n, int tok, int par,
    const float* bias1, const float* xg0d,
    int barslot, unsigned barnb, unsigned& sense)
{
    const int K = LAYER ? (Hc + H2) : Hc;
    int slot = LAYER ? (2 + dir) : dir;
    const float* hglob = &g_hst[slot][par][0];
    float* hout = &g_hst[slot][par ^ 1][0];
    float* cst  = &g_cst[slot][0];
    const float* WT = LAYER ? (g_W1T + (size_t)dir * H4 * (Hc + H2))
                            : (g_W0T + (size_t)dir * H4 * Hc);

    // stage A: stage h (and x1 for layer1) into bank-swizzled smem
    {
        const float* x1g = g_x1 + (size_t)tok * H2 * Bc;
        int nf4 = K * 4;
        for (int idx = tid; idx < nf4; idx += 256) {
            int k = idx >> 2, q = idx & 3;
            float4 v;
            if (!LAYER || k < Hc) v = *(const float4*)&hglob[k * Bc + q * 4];
            else                  v = *(const float4*)&x1g[(size_t)(k - Hc) * Bc + q * 4];
            *(float4*)(hsb + hs_off(k, q)) = v;
        }
    }
    __syncthreads();

    // stage B: 8 rows per thread (consecutive m), 16 k-slices, double-buffered weights
    const float4* pw = (const float4*)(WT + (size_t)(rg * Hc + bkid * 8) * K);
    const int RS = K / 4;            // f4 row stride
    const int KI = K / 64;           // chunks (8 or 24)

    unsigned long long acc0[8], acc1[8];
    #pragma unroll
    for (int j = 0; j < 8; j++) { acc0[j] = 0ull; acc1[j] = 0ull; }

    float4 cur[8], nxt[8];
    #pragma unroll
    for (int j = 0; j < 8; j++) cur[j] = pw[j * RS + ksub];

    #pragma unroll 2
    for (int i = 0; i < KI; i++) {
        int nf = ((i + 1 < KI) ? (i + 1) : i) * 16 + ksub;
        #pragma unroll
        for (int j = 0; j < 8; j++) nxt[j] = pw[j * RS + nf];
        int kb = i * 64 + ksub * 4;
        #pragma unroll
        for (int kk = 0; kk < 4; kk++) {
            ulonglong2 hv = *(const ulonglong2*)(hsb + hs_off(kb + kk, bs));
            #pragma unroll
            for (int j = 0; j < 8; j++) {
                unsigned long long s = splat2(((const float*)&cur[j])[kk]);
                FMA2(acc0[j], s, hv.x);
                FMA2(acc1[j], s, hv.y);
            }
        }
        #pragma unroll
        for (int j = 0; j < 8; j++) cur[j] = nxt[j];
    }

    // stage C: dump partials; acc0 = (b0,b1), acc1 = (b2,b3) for each row
    #pragma unroll
    for (int j = 0; j < 8; j++) {
        int row = rg * 8 + j;
        float4 v = make_float4(f2lo(acc0[j]), f2hi(acc0[j]),
                               f2lo(acc1[j]), f2hi(acc1[j]));
        *(float4*)(redb + row * RED_ROWSTRIDE + ksub * 80 + bs * 16) = v;
    }
    __syncthreads();

    // stage D: reduce over 16 ksub + nonlinearity + state update
    if (tid < 128) {
        int ko_l = tid & 7, b = tid >> 3;
        int ko = bkid * 8 + ko_l;
        float gsum[4];
        #pragma unroll
        for (int g = 0; g < 4; g++) {
            int row = g * 8 + ko_l;
            const char* base = redb + row * RED_ROWSTRIDE;
            float ss = 0.f;
            #pragma unroll
            for (int ks = 0; ks < 16; ks++)
                ss += ((const float*)(base + ks * 80))[b];
            gsum[g] = ss;
        }
        float pi, pf, pg, po;
        if (LAYER) {
            pi = bias1[ko]; pf = bias1[512 + ko];
            pg = bias1[1024 + ko]; po = bias1[1536 + ko];
        } else {
            const float* xg = xg0d + ((size_t)(n * Tc + tok) * Bc + b) * H4 + ko;
            pi = xg[0]; pf = xg[512]; pg = xg[1024]; po = xg[1536];
        }
        float gi = gsum[0] + pi, gf = gsum[1] + pf, gg = gsum[2] + pg, go = gsum[3] + po;
        float si = 1.f / (1.f + expf(-gi));
        float sf = 1.f / (1.f + expf(-gf));
        float so = 1.f / (1.f + expf(-go));
        int idx = ko * Bc + b;
        float cn = sf * cst[idx] + si * tanhf(gg);
        float hn = so * tanhf(cn);
        cst[idx]  = cn;
        hout[idx] = hn;
        if (LAYER) {
            g_out1[((size_t)(n * Tc + tok) * Bc + b) * H2 + dir * Hc + ko] = hn;
        } else {
            g_x1[((size_t)tok * H2 + dir * Hc + ko) * Bc + b] = hn;
        }
    }
    gbar(barslot, barnb, sense);
}

#define HS_BYTES ((Hc + H2) * 64)          // 98304
#define LSTM_SMEM (HS_BYTES + RED_BYTES)   // 139264

__global__ __launch_bounds__(256, 1) void lstm_persist(
    const float* __restrict__ b1f_, const float* __restrict__ b1b_)
{
    extern __shared__ __align__(16) char smemc[];
    char* hsb  = smemc;
    char* redb = smemc + HS_BYTES;

    int tid = threadIdx.x, bid = blockIdx.x;
    int dir = bid >> 6, bkid = bid & 63;
    // warp-friendly mapping: all 4 bs duplicates in-warp, ksub_h = bit 5
    int ksub = (tid & 7) | (((tid >> 5) & 1) << 3);
    int bs   = (tid >> 3) & 3;
    int rg   = tid >> 6;

    const float* bias1 = dir ? b1b_ : b1f_;
    const float* xg0d  = g_xg0 + (size_t)dir * NTB * H4;

    unsigned sdir = 0, sfull = 0;
    int p0 = 0, p1 = 0;

    for (int t = 0; t < Tc; t++) {
        for (int n = 0; n < Nc; n++) {
            int L = t + 1;
            for (int s = 0; s < L; s++) {
                int tok = dir ? (L - 1 - s) : s;
                bool last = (s == L - 1);
                lstm_do_step<0>(tid, dir, bkid, ksub, bs, rg, hsb, redb,
                                n, tok, p0, bias1, xg0d,
                                last ? 2 : dir, last ? 128u : 64u,
                                last ? sfull : sdir);
                p0 ^= 1;
            }
            for (int s = 0; s < L; s++) {
                int tok = dir ? (L - 1 - s) : s;
                bool last = (s == L - 1);
                lstm_do_step<1>(tid, dir, bkid, ksub, bs, rg, hsb, redb,
                                n, tok, p1, bias1, xg0d,
                                last ? 2 : dir, last ? 128u : 64u,
                                last ? sfull : sdir);
                p1 ^= 1;
            }
        }
    }

    // fused convA: out1 -> bf16 hi/lo (all out1 writes visible after final full barrier)
    for (int i = bid * 256 + tid; i < NTB * H2; i += NBLK * 256) {
        float v = g_out1[i];
        __nv_bfloat16 h = __float2bfloat16(v);
        g_Ahi[i] = h;
        g_Alo[i] = __float2bfloat16(v - __bfloat162float(h));
    }
}

// ================= bf16-split mma.sync FC =================
#define FCBM 128
#define FCBN 128
#define FCBK 64
#define PADK 72
#define FC_SMEM (4 * FCBM * PADK * 2)

__device__ __forceinline__ void mma16816(
    float& c0, float& c1, float& c2, float& c3,
    uint32_t a0, uint32_t a1, uint32_t a2, uint32_t a3,
    uint32_t b0, uint32_t b1)
{
    asm volatile(
        "mma.sync.aligned.m16n8k16.row.col.f32.bf16.bf16.f32 "
        "{%0,%1,%2,%3}, {%4,%5,%6,%7}, {%8,%9}, {%0,%1,%2,%3};"
        : "+f"(c0), "+f"(c1), "+f"(c2), "+f"(c3)
        : "r"(a0), "r"(a1), "r"(a2), "r"(a3), "r"(b0), "r"(b1));
}

__global__ __launch_bounds__(256) void fc_wmma(
    const float* __restrict__ bias, float* __restrict__ out)
{
    extern __shared__ __align__(16) __nv_bfloat16 sm[];
    __nv_bfloat16* sAh = sm;
    __nv_bfloat16* sAl = sm + FCBM * PADK;
    __nv_bfloat16* sBh = sm + 2 * FCBM * PADK;
    __nv_bfloat16* sBl = sm + 3 * FCBM * PADK;

    int tid = threadIdx.x;
    int wid = tid >> 5, lane = tid & 31;
    int g = lane >> 2, q = lane & 3;
    int wm = wid & 3, wn = wid >> 2;
    int bm = blockIdx.y * FCBM, bn = blockIdx.x * FCBN;

    const uint4* A4h = (const uint4*)g_Ahi;
    const uint4* A4l = (const uint4*)g_Alo;
    const uint4* B4h = (const uint4*)g_Bhi;
    const uint4* B4l = (const uint4*)g_Blo;
    const uint4 z4 = make_uint4(0, 0, 0, 0);

    float acc[2][8][4];
    #pragma unroll
    for (int i = 0; i < 2; i++)
        #pragma unroll
        for (int j = 0; j < 8; j++)
            #pragma unroll
            for (int e = 0; e < 4; e++) acc[i][j][e] = 0.f;

    const uint32_t* sA32h = (const uint32_t*)sAh;
    const uint32_t* sA32l = (const uint32_t*)sAl;
    const uint32_t* sB32h = (const uint32_t*)sBh;
    const uint32_t* sB32l = (const uint32_t*)sBl;

    for (int kc = 0; kc < H2 / FCBK; kc++) {
        __syncthreads();
        #pragma unroll
        for (int it = 0; it < 4; it++) {
            int idx = tid + it * 256;
            int m = idx >> 3, kg = idx & 7;
            int gm = bm + m;
            size_t gi = (size_t)gm * (H2 / 8) + kc * 8 + kg;
            uint4 vh = z4, vl = z4;
            if (gm < NTB) { vh = A4h[gi]; vl = A4l[gi]; }
            *(uint4*)&sAh[m * PADK + kg * 8] = vh;
            *(uint4*)&sAl[m * PADK + kg * 8] = vl;
        }
        #pragma unroll
        for (int it = 0; it < 4; it++) {
            int idx = tid + it * 256;
            int n = idx >> 3, kg = idx & 7;
            int gn = bn + n;
            uint4 vh = z4, vl = z4;
            if (gn < Vc) {
                size_t gi = (size_t)gn * (H2 / 8) + kc * 8 + kg;
                vh = B4h[gi]; vl = B4l[gi];
            }
            *(uint4*)&sBh[n * PADK + kg * 8] = vh;
            *(uint4*)&sBl[n * PADK + kg * 8] = vl;
        }
        __syncthreads();

        #pragma unroll
        for (int ks = 0; ks < 4; ks++) {
            uint32_t ah[2][4], al[2][4];
            #pragma unroll
            for (int mi = 0; mi < 2; mi++) {
                int r0 = (wm * 32 + mi * 16 + g) * (PADK / 2);
                int r8 = r0 + 8 * (PADK / 2);
                int w0 = ks * 8 + q, w4 = w0 + 4;
                ah[mi][0] = sA32h[r0 + w0]; ah[mi][1] = sA32h[r8 + w0];
                ah[mi][2] = sA32h[r0 + w4]; ah[mi][3] = sA32h[r8 + w4];
                al[mi][0] = sA32l[r0 + w0]; al[mi][1] = sA32l[r8 + w0];
                al[mi][2] = sA32l[r0 + w4]; al[mi][3] = sA32l[r8 + w4];
            }
            #pragma unroll
            for (int ni = 0; ni < 8; ni++) {
                int nr = (wn * 64 + ni * 8 + g) * (PADK / 2);
                int w0 = ks * 8 + q, w4 = w0 + 4;
                uint32_t bh0 = sB32h[nr + w0], bh1 = sB32h[nr + w4];
                uint32_t bl0 = sB32l[nr + w0], bl1 = sB32l[nr + w4];
                #pragma unroll
                for (int mi = 0; mi < 2; mi++) {
                    float* c = acc[mi][ni];
                    mma16816(c[0], c[1], c[2], c[3],
                             ah[mi][0], ah[mi][1], ah[mi][2], ah[mi][3], bh0, bh1);
                    mma16816(c[0], c[1], c[2], c[3],
                             al[mi][0], al[mi][1], al[mi][2], al[mi][3], bh0, bh1);
                    mma16816(c[0], c[1], c[2], c[3],
                             ah[mi][0], ah[mi][1], ah[mi][2], ah[mi][3], bl0, bl1);
                }
            }
        }
    }

    #pragma unroll
    for (int mi = 0; mi < 2; mi++) {
        int row0 = bm + wm * 32 + mi * 16 + g;
        int row1 = row0 + 8;
        #pragma unroll
        for (int ni = 0; ni < 8; ni++) {
            int col = bn + wn * 64 + ni * 8 + q * 2;
            if (col >= Vc) continue;
            float b0 = bias[col], b1 = bias[col + 1];
            const float* c = acc[mi][ni];
            if (row0 < NTB) {
                float2 v = make_float2(c[0] + b0, c[1] + b1);
                *(float2*)&out[(size_t)row0 * Vc + col] = v;
            }
            if (row1 < NTB) {
                float2 v = make_float2(c[2] + b0, c[3] + b1);
                *(float2*)&out[(size_t)row1 * Vc + col] = v;
            }
        }
    }
}

// ---------------- host ----------------
extern "C" void kernel_launch(void* const* d_in, const int* in_sizes, int n_in,
                              void* d_out, int out_size)
{
    const float* img   = (const float*)d_in[0];
    const int*   caps  = (const int*)  d_in[1];
    const float* Wh1   = (const float*)d_in[2];
    const float* bh1   = (const float*)d_in[3];
    const float* Wh2   = (const float*)d_in[4];
    const float* bh2   = (const float*)d_in[5];
    const float* Wc1   = (const float*)d_in[6];
    const float* bc1   = (const float*)d_in[7];
    const float* Wc2   = (const float*)d_in[8];
    const float* bc2   = (const float*)d_in[9];
    const float* emb   = (const float*)d_in[10];
    const float* Wih0f = (const float*)d_in[11];
    const float* Whh0f = (const float*)d_in[12];
    const float* b0f   = (const float*)d_in[13];
    const float* Wih0b = (const float*)d_in[14];
    const float* Whh0b = (const float*)d_in[15];
    const float* b0b   = (const float*)d_in[16];
    const float* Wih1f = (const float*)d_in[17];
    const float* Whh1f = (const float*)d_in[18];
    const float* b1f   = (const float*)d_in[19];
    const float* Wih1b = (const float*)d_in[20];
    const float* Whh1b = (const float*)d_in[21];
    const float* b1b   = (const float*)d_in[22];
    const float* Wfc   = (const float*)d_in[23];
    const float* bfc   = (const float*)d_in[24];
    float* outp = (float*)d_out;

    float *p_W0T, *p_W1T;
    cudaGetSymbolAddress((void**)&p_W0T,  g_W0T);
    cudaGetSymbolAddress((void**)&p_W1T,  g_W1T);

    const size_t W1ROW = (size_t)H4 * (Hc + H2);

    // Launch 0: transposes + MLP stage1 + gather + convB (fused 1-D dispatch)
    TParams6 tp;
    tp.p[0] = { Whh0f, p_W0T,                 Hc, Hc };
    tp.p[1] = { Whh0b, p_W0T + (size_t)H4*Hc, Hc, Hc };
    tp.p[2] = { Whh1f, p_W1T,                 Hc, Hc + H2 };
    tp.p[3] = { Wih1f, p_W1T + Hc,            H2, Hc + H2 };
    tp.p[4] = { Whh1b, p_W1T + W1ROW,         Hc, Hc + H2 };
    tp.p[5] = { Wih1b, p_W1T + W1ROW + Hc,    H2, Hc + H2 };
    pre1<<<P1_TOTAL, 256>>>(tp, img, Wh1, bh1, Wc1, bc1, caps, emb, Wfc);

    // Launch 1: MLP stage2 (dual)
    pre2k<<<dim3(Hc/64, 1, 2), 256>>>(Wh2, bh2, Wc2, bc2);

    // Launch 2: xg0 GEMMs (z=0,1) + k-major state broadcast (z=2)
    pre3<<<dim3(H4/128, (NTB+127)/128, 3), 256>>>(Wih0f, b0f, Wih0b, b0b);

    // Launch 3: persistent recurrent chain (per-dir barriers; full at loop boundaries)
    cudaFuncSetAttribute(lstm_persist, cudaFuncAttributeMaxDynamicSharedMemorySize, LSTM_SMEM);
    lstm_persist<<<NBLK, 256, LSTM_SMEM>>>(b1f, b1b);

    // Launch 4: tensor-core FC
    cudaFuncSetAttribute(fc_wmma, cudaFuncAttributeMaxDynamicSharedMemorySize, FC_SMEM);
    fc_wmma<<<dim3((Vc + FCBN - 1)/FCBN, (NTB + FCBM - 1)/FCBM), 256, FC_SMEM>>>(bfc, outp);
}

// round 16
// speedup vs baseline: 1.2849x; 1.2155x over previous
#include <cuda_runtime.h>
#include <cuda_bf16.h>
#include <math.h>
#include <stdint.h>

// Problem constants
#define Bc 16
#define Nc 5
#define Tc 10
#define Hc 512
#define Ec 250
#define Vc 30000
#define Fc 2048
#define H4 2048
#define H2 1024
#define NTB (Nc*Tc*Bc)   // 800
#define NBLK 128
#define HPAD 772         // hsm row stride in uint32 (772 mod 32 = 4 -> conflict-free b-frags)

// packed fp32x2 FMA (SASS FFMA2) — still used by fp32 GEMMs
#define FMA2(d, a, b) asm("fma.rn.f32x2 %0, %1, %2, %0;" : "+l"(d) : "l"(a), "l"(b))

__device__ __forceinline__ float f2lo(unsigned long long v) { return __uint_as_float((unsigned)v); }
__device__ __forceinline__ float f2hi(unsigned long long v) { return __uint_as_float((unsigned)(v >> 32)); }

// pack two f32 -> bf16x2 (lo in lower half, hi in upper half)
__device__ __forceinline__ uint32_t pkbf(float lo, float hi) {
    uint32_t r;
    asm("cvt.rn.bf16x2.f32 %0, %1, %2;" : "=r"(r) : "f"(hi), "f"(lo));
    return r;
}

// ---------------- device scratch ----------------
__device__ __align__(16) float g_tmp[Bc*H2];
__device__ __align__(16) float g_tmp2[Bc*H2];
__device__ __align__(16) float g_h0[Bc*Hc];          // [b][k]
__device__ __align__(16) float g_c0[Bc*Hc];          // [b][k]
__device__ __align__(16) float g_hst[4][2][Bc*Hc];   // state h, b-major [b][k]
__device__ __align__(16) float g_cst[4][Bc*Hc];      // state c, b-major
__device__ __align__(16) float g_x0[NTB*Ec];
__device__ __align__(16) float g_xg0[2*NTB*H4];
__device__ __align__(16) float g_x1[Tc*Bc*H2];       // [t][b][1024] b-major
__device__ __align__(16) float g_out1[NTB*H2];
__device__ __align__(16) float g_W0T[2*H4*Hc];
__device__ __align__(16) float g_W1T[2*H4*(Hc+H2)];
// fragment-linear split-bf16 weights: [dir][bkid][kq][ks][mt][plane][lane] uint4
#define W0F_DIR 262144
#define W1F_DIR 786432
__device__ __align__(16) uint4 g_W0F[2*W0F_DIR];
__device__ __align__(16) uint4 g_W1F[2*W1F_DIR];
__device__ __align__(16) __nv_bfloat16 g_Ahi[NTB*H2];
__device__ __align__(16) __nv_bfloat16 g_Alo[NTB*H2];
__device__ __align__(16) __nv_bfloat16 g_Bhi[(size_t)Vc*H2];
__device__ __align__(16) __nv_bfloat16 g_Blo[(size_t)Vc*H2];

// barrier state: slot 0 = dir0 (64 blocks), slot 1 = dir1 (64), slot 2 = full (128)
__device__ __align__(128) unsigned g_cnt[96];
__device__ __align__(128) unsigned g_sns[96];

// ---------------- shared sgemm body (64x64 tiles) ----------------
struct TParam { const float* in; float* out; int R; int ostride; };
struct TParams6 { TParam p[6]; };

__device__ __forceinline__ void sgemm_body(
    const float* A, const float* W, const float* bias, float* C,
    int M, int N, int K, int relu, int bm, int bn, int tid,
    float* As, float* Bs)
{
    int tm = (tid >> 4) << 2;
    int tn = (tid & 15) << 2;
    float acc[4][4] = {};
    for (int k0 = 0; k0 < K; k0 += 16) {
        #pragma unroll
        for (int e = 0; e < 4; e++) {
            int idx = tid + e * 256;
            int r = idx >> 4, c = idx & 15;
            int gr = bm + r, gc = k0 + c;
            As[c * 64 + r] = (gr < M && gc < K) ? A[(size_t)gr * K + gc] : 0.f;
        }
        #pragma unroll
        for (int e = 0; e < 4; e++) {
            int idx = tid + e * 256;
            int r = idx >> 6, c = idx & 63;
            int gr = k0 + r, gc = bn + c;
            Bs[r * 64 + c] = (gr < K && gc < N) ? W[(size_t)gr * N + gc] : 0.f;
        }
        __syncthreads();
        #pragma unroll
        for (int kk = 0; kk < 16; kk++) {
            float4 a4 = *(const float4*)&As[kk * 64 + tm];
            float4 b4 = *(const float4*)&Bs[kk * 64 + tn];
            float a[4] = {a4.x, a4.y, a4.z, a4.w};
            float b[4] = {b4.x, b4.y, b4.z, b4.w};
            #pragma unroll
            for (int i = 0; i < 4; i++)
                #pragma unroll
                for (int j = 0; j < 4; j++)
                    acc[i][j] = fmaf(a[i], b[j], acc[i][j]);
        }
        __syncthreads();
    }
    #pragma unroll
    for (int i = 0; i < 4; i++) {
        int gm = bm + tm + i;
        if (gm >= M) continue;
        #pragma unroll
        for (int j = 0; j < 4; j++) {
            int gn = bn + tn + j;
            if (gn >= N) continue;
            float v = acc[i][j] + bias[gn];
            if (relu) v = fmaxf(v, 0.f);
            C[(size_t)gm * N + gn] = v;
        }
    }
}

// ================= pre1: transposes + MLP stage1 + gather + convB =================
#define P1_TRANS 12288           // 6 * 64 * 32
#define P1_MLP   (P1_TRANS + 32)
#define P1_GATH  (P1_MLP + 800)
#define P1_TOTAL (P1_GATH + 30016)

__global__ __launch_bounds__(256) void pre1(
    TParams6 tp,
    const float* __restrict__ img,
    const float* __restrict__ Wh1, const float* __restrict__ bh1,
    const float* __restrict__ Wc1, const float* __restrict__ bc1,
    const int* __restrict__ caps, const float* __restrict__ emb,
    const float* __restrict__ Wfc)
{
    __shared__ float sh[2048];
    int id = blockIdx.x, tid = threadIdx.x;
    int tx = tid & 31, ty = tid >> 5;

    if (id < P1_TRANS) {
        int which = id / 2048, rem = id % 2048;
        int bx = rem & 63, by = rem >> 6;
        TParam p = tp.p[which];
        int c0 = bx * 32, r0 = by * 32;
        if (r0 >= p.R) return;
        for (int j = ty; j < 32; j += 8) {
            int r = r0 + j, c = c0 + tx;
            sh[j * 33 + tx] = (r < p.R) ? p.in[(size_t)r * H4 + c] : 0.f;
        }
        __syncthreads();
        for (int j = ty; j < 32; j += 8) {
            int c = c0 + j, r = r0 + tx;
            if (r < p.R) p.out[(size_t)c * p.ostride + r] = sh[tx * 33 + j];
        }
    } else if (id < P1_MLP) {
        int sub = id - P1_TRANS;
        int z = sub >> 4, bx = sub & 15;
        sgemm_body(img, z ? Wc1 : Wh1, z ? bc1 : bh1, z ? g_tmp2 : g_tmp,
                   Bc, H2, Fc, 1, 0, bx * 64, tid, sh, sh + 1024);
    } else if (id < P1_GATH) {
        int rid = id - P1_MLP;
        int b = rid & 15;
        int nt = rid >> 4;
        int n = nt / Tc, t = nt % Tc;
        int tok = caps[b * (Nc * Tc) + n * Tc + t];
        const float* e = emb + (size_t)tok * Ec;
        float* o = g_x0 + (size_t)rid * Ec;
        for (int i = tid; i < Ec; i += 256) o[i] = e[i];
    } else {
        int sub = id - P1_GATH;
        int n0 = (sub % 938) * 32, k0 = (sub / 938) * 32;
        for (int j = ty; j < 32; j += 8) {
            int k = k0 + j, n = n0 + tx;
            sh[j * 33 + tx] = (n < Vc) ? Wfc[(size_t)k * Vc + n] : 0.f;
        }
        __syncthreads();
        for (int j = ty; j < 32; j += 8) {
            int n = n0 + j, k = k0 + tx;
            if (n < Vc) {
                float v = sh[tx * 33 + j];
                __nv_bfloat16 h = __float2bfloat16(v);
                g_Bhi[(size_t)n * H2 + k] = h;
                g_Blo[(size_t)n * H2 + k] = __float2bfloat16(v - __bfloat162float(h));
            }
        }
    }
}

// ================= wfrag: W0T/W1T -> fragment-linear split-bf16 =================
// threads: L0: 2dir*64*4kq*8ks*2mt*32 = 262144; L1: 786432; total 1048576
__global__ __launch_bounds__(256) void wfrag()
{
    int u = blockIdx.x * 256 + threadIdx.x;
    int layer = (u >= 262144);
    if (layer) u -= 262144;
    const int KS = layer ? 24 : 8;
    const int K  = layer ? (Hc + H2) : Hc;
    int lane = u & 31;
    int mt = (u >> 5) & 1;
    int rest = u >> 6;
    int ks = rest % KS; rest /= KS;
    int kq = rest & 3;  rest >>= 2;
    int bkid = rest & 63;
    int dir = rest >> 6;
    int g = lane >> 2, q = lane & 3;

    const float* WT = layer ? (g_W1T + (size_t)dir * H4 * (Hc + H2))
                            : (g_W0T + (size_t)dir * H4 * Hc);
    int kk = (kq * KS + ks) * 16;
    int r0 = mt * 1024 + bkid * 8 + g;   // gate mt*2,   ko_l g
    int r1 = r0 + 512;                   // gate mt*2+1, ko_l g
    float2 w0 = *(const float2*)&WT[(size_t)r0 * K + kk + 2 * q];
    float2 w1 = *(const float2*)&WT[(size_t)r1 * K + kk + 2 * q];
    float2 w2 = *(const float2*)&WT[(size_t)r0 * K + kk + 2 * q + 8];
    float2 w3 = *(const float2*)&WT[(size_t)r1 * K + kk + 2 * q + 8];

    uint4 hi, lo;
    hi.x = pkbf(w0.x, w0.y);
    hi.y = pkbf(w1.x, w1.y);
    hi.z = pkbf(w2.x, w2.y);
    hi.w = pkbf(w3.x, w3.y);
    lo.x = pkbf(w0.x - __uint_as_float(hi.x << 16), w0.y - __uint_as_float(hi.x & 0xFFFF0000u));
    lo.y = pkbf(w1.x - __uint_as_float(hi.y << 16), w1.y - __uint_as_float(hi.y & 0xFFFF0000u));
    lo.z = pkbf(w2.x - __uint_as_float(hi.z << 16), w2.y - __uint_as_float(hi.z & 0xFFFF0000u));
    lo.w = pkbf(w3.x - __uint_as_float(hi.w << 16), w3.y - __uint_as_float(hi.w & 0xFFFF0000u));

    uint4* dst = (layer ? g_W1F : g_W0F)
               + (size_t)dir * (layer ? W1F_DIR : W0F_DIR)
               + ((size_t)((bkid * 4 + kq) * KS + ks) * 4 + mt * 2) * 32 + lane;
    dst[0]  = hi;
    dst[32] = lo;
}

// ================= pre2: MLP stage2 (dual via z) =================
__global__ __launch_bounds__(256) void pre2k(
    const float* __restrict__ Wh2, const float* __restrict__ bh2,
    const float* __restrict__ Wc2, const float* __restrict__ bc2)
{
    __shared__ float sh[2048];
    int z = blockIdx.z;
    sgemm_body(z ? g_tmp2 : g_tmp, z ? Wc2 : Wh2, z ? bc2 : bh2, z ? g_c0 : g_h0,
               Bc, Hc, H2, 1, 0, blockIdx.x * 64, threadIdx.x, sh, sh + 1024);
}

// ================= pre3: xg0 GEMM (z=0,1) + state broadcast b-major (z=2) =================
__global__ __launch_bounds__(256) void pre3(
    const float* __restrict__ B0, const float* __restrict__ bias0,
    const float* __restrict__ B1, const float* __restrict__ bias1)
{
    __shared__ __align__(16) float As[2][16][128];
    __shared__ __align__(16) float Bs[2][16][256];

    if (blockIdx.z == 2) {
        int lin = blockIdx.y * 16 + blockIdx.x;
        if (lin < 32) {
            int i = lin * 256 + threadIdx.x;   // b-major copy
            float h = g_h0[i];
            float c = g_c0[i];
            #pragma unroll
            for (int s = 0; s < 4; s++) {
                g_hst[s][0][i] = h;
                g_cst[s][i]    = c;
            }
        }
        return;
    }

    const float* A = g_x0;
    const float* B = blockIdx.z ? B1 : B0;
    const float* bias = blockIdx.z ? bias1 : bias0;
    float* C = blockIdx.z ? (g_xg0 + (size_t)NTB * H4) : g_xg0;
    const int M = NTB, N = H4, K = Ec;

    int tid = threadIdx.x;
    int bm = blockIdx.y * 128, bn = blockIdx.x * 128;
    int tx = tid & 15, ty = tid >> 4;
    int ar = tid >> 2, ac = (tid & 3) * 4;
    int br = tid >> 5, bc = (tid & 31) * 4;

    unsigned long long acc[4][8];
    #pragma unroll
    for (int i = 0; i < 4; i++)
        #pragma unroll
        for (int j = 0; j < 8; j++) acc[i][j] = 0ull;

    float a0[4], a1[4], b0[4], b1[4];
    int KT = (K + 15) / 16;

#define LOADTILE(KT_) do {                                                        \
    int k0 = (KT_) * 16;                                                          \
    int gr0 = bm + ar, gr1 = bm + ar + 64;                                        \
    _Pragma("unroll") for (int j = 0; j < 4; j++) {                               \
        int gk = k0 + ac + j;                                                     \
        bool ok = (gk < K);                                                       \
        a0[j] = (ok && gr0 < M) ? A[(size_t)gr0 * K + gk] : 0.f;                  \
        a1[j] = (ok && gr1 < M) ? A[(size_t)gr1 * K + gk] : 0.f;                  \
    }                                                                             \
    int gk0 = k0 + br, gk1 = k0 + br + 8;                                         \
    _Pragma("unroll") for (int j = 0; j < 4; j++) {                               \
        int gc = bn + bc + j;                                                     \
        b0[j] = (gk0 < K) ? B[(size_t)gk0 * N + gc] : 0.f;                        \
        b1[j] = (gk1 < K) ? B[(size_t)gk1 * N + gc] : 0.f;                        \
    }                                                                             \
} while (0)

#define STORETILE(BUF_) do {                                                      \
    _Pragma("unroll") for (int j = 0; j < 4; j++) {                               \
        As[BUF_][ac + j][ar]      = a0[j];                                        \
        As[BUF_][ac + j][ar + 64] = a1[j];                                        \
        Bs[BUF_][br][(bc + j) * 2]         = b0[j];                               \
        Bs[BUF_][br][(bc + j) * 2 + 1]     = b0[j];                               \
        Bs[BUF_][br + 8][(bc + j) * 2]     = b1[j];                               \
        Bs[BUF_][br + 8][(bc + j) * 2 + 1] = b1[j];                               \
    }                                                                             \
} while (0)

    LOADTILE(0);
    STORETILE(0);
    __syncthreads();

    for (int kt = 0; kt < KT; kt++) {
        int cur = kt & 1;
        if (kt + 1 < KT) LOADTILE(kt + 1);
        #pragma unroll
        for (int k = 0; k < 16; k++) {
            unsigned long long a2[4], b2[8];
            #pragma unroll
            for (int i = 0; i < 4; i++)
                a2[i] = *(const unsigned long long*)&As[cur][k][ty * 8 + 2 * i];
            #pragma unroll
            for (int j = 0; j < 8; j++)
                b2[j] = *(const unsigned long long*)&Bs[cur][k][(tx + 16 * j) * 2];
            #pragma unroll
            for (int i = 0; i < 4; i++)
                #pragma unroll
                for (int j = 0; j < 8; j++)
                    FMA2(acc[i][j], a2[i], b2[j]);
        }
        if (kt + 1 < KT) STORETILE(cur ^ 1);
        __syncthreads();
    }

    #pragma unroll
    for (int j = 0; j < 8; j++) {
        int col = bn + tx + 16 * j;
        float bb = bias[col];
        #pragma unroll
        for (int i = 0; i < 4; i++) {
            int r0 = bm + ty * 8 + 2 * i;
            float lo = f2lo(acc[i][j]) + bb;
            float hi = f2hi(acc[i][j]) + bb;
            if (r0 < M)     C[(size_t)r0 * N + col] = lo;
            if (r0 + 1 < M) C[(size_t)(r0 + 1) * N + col] = hi;
        }
    }
#undef LOADTILE
#undef STORETILE
}

// ================= mma.sync helper (shared with FC) =================
__device__ __forceinline__ void mma16816(
    float& c0, float& c1, float& c2, float& c3,
    uint32_t a0, uint32_t a1, uint32_t a2, uint32_t a3,
    uint32_t b0, uint32_t b1)
{
    asm volatile(
        "mma.sync.aligned.m16n8k16.row.col.f32.bf16.bf16.f32 "
        "{%0,%1,%2,%3}, {%4,%5,%6,%7}, {%8,%9}, {%0,%1,%2,%3};"
        : "+f"(c0), "+f"(c1), "+f"(c2), "+f"(c3)
        : "r"(a0), "r"(a1), "r"(a2), "r"(a3), "r"(b0), "r"(b1));
}

// ================= persistent recurrent kernel (tensor-core stage B) =================
__device__ __forceinline__ void gbar(int slot, unsigned nb, unsigned& sense)
{
    __syncthreads();
    sense ^= 1;
    if (threadIdx.x == 0) {
        unsigned* c = &g_cnt[slot * 32];
        unsigned* s = &g_sns[slot * 32];
        __threadfence();
        unsigned old = atomicAdd(c, 1);
        if (old == nb - 1) {
            *c = 0;
            __threadfence();
            atomicExch(s, sense);
        } else {
            while (*(volatile unsigned*)s != sense) __nanosleep(32);
        }
        __threadfence();
    }
    __syncthreads();
}

#define HS_U32   (16 * HPAD)               // per plane
#define HS_BYTES (HS_U32 * 4 * 2)          // 98816 (hi + lo)
#define RED_FLOATS 2048                    // 2mt*2nt*4kq*32lane*4
#define LSTM_SMEM (HS_BYTES + RED_FLOATS * 4)   // 107008

template<int LAYER>
__device__ __forceinline__ void lstm_do_step(
    int tid, int dir, int bkid,
    uint32_t* hsmH, uint32_t* hsmL, float* red,
    int n, int tok, int par,
    const float* bias1, const float* xg0d,
    int barslot, unsigned barnb, unsigned& sense)
{
    const int K  = LAYER ? (Hc + H2) : Hc;
    const int KS = LAYER ? 24 : 8;
    const int Q  = K / 4;                   // f4 per batch row
    int slot = LAYER ? (2 + dir) : dir;
    const float* hglob = &g_hst[slot][par][0];   // [b*Hc + k]
    float* hout = &g_hst[slot][par ^ 1][0];
    float* cst  = &g_cst[slot][0];

    // ---- stage A: h (and x1) -> smem bf16 hi/lo, [b][k], row stride HPAD u32 ----
    {
        const float* x1g = g_x1 + (size_t)tok * Bc * H2;   // [b*H2 + k]
        for (int idx = tid; idx < 4 * K; idx += 256) {
            int b = idx / Q, k4 = idx % Q;
            int k = k4 * 4;
            float4 v;
            if (!LAYER || k < Hc) v = *(const float4*)&hglob[b * Hc + k];
            else                  v = *(const float4*)&x1g[b * H2 + (k - Hc)];
            uint32_t h01 = pkbf(v.x, v.y), h23 = pkbf(v.z, v.w);
            float r0 = v.x - __uint_as_float(h01 << 16);
            float r1 = v.y - __uint_as_float(h01 & 0xFFFF0000u);
            float r2 = v.z - __uint_as_float(h23 << 16);
            float r3 = v.w - __uint_as_float(h23 & 0xFFFF0000u);
            int off = b * HPAD + k4 * 2;
            *(uint2*)&hsmH[off] = make_uint2(h01, h23);
            *(uint2*)&hsmL[off] = make_uint2(pkbf(r0, r1), pkbf(r2, r3));
        }
    }
    __syncthreads();

    // ---- stage B: split-bf16 mma; warp = (mt, kq); G[32m][16b] partials ----
    int wid = tid >> 5, lane = tid & 31;
    int mt = wid & 1, kq = wid >> 1;
    int g = lane >> 2, q = lane & 3;
    const uint4* WF = (LAYER ? g_W1F : g_W0F)
                    + (size_t)dir * (LAYER ? W1F_DIR : W0F_DIR)
                    + (size_t)(bkid * 4 + kq) * (KS * 128) + lane;
    float c[2][4] = {};
    for (int ks = 0; ks < KS; ks++) {
        const uint4* pa = WF + (size_t)(ks * 4 + mt * 2) * 32;
        uint4 AH = pa[0];
        uint4 AL = pa[32];
        int kp = (kq * KS + ks) * 8 + q;
        #pragma unroll
        for (int nt = 0; nt < 2; nt++) {
            int rb = (nt * 8 + g) * HPAD + kp;
            uint32_t bh0 = hsmH[rb], bh1 = hsmH[rb + 4];
            uint32_t bl0 = hsmL[rb], bl1 = hsmL[rb + 4];
            mma16816(c[nt][0], c[nt][1], c[nt][2], c[nt][3],
                     AH.x, AH.y, AH.z, AH.w, bh0, bh1);
            mma16816(c[nt][0], c[nt][1], c[nt][2], c[nt][3],
                     AL.x, AL.y, AL.z, AL.w, bh0, bh1);
            mma16816(c[nt][0], c[nt][1], c[nt][2], c[nt][3],
                     AH.x, AH.y, AH.z, AH.w, bl0, bl1);
        }
    }

    // ---- stage C: dump partials ----
    #pragma unroll
    for (int nt = 0; nt < 2; nt++) {
        *(float4*)&red[(((mt * 2 + nt) * 4 + kq) * 32 + lane) * 4] =
            make_float4(c[nt][0], c[nt][1], c[nt][2], c[nt][3]);
    }
    __syncthreads();

    // ---- stage D: reduce 4 k-quarters + nonlinearity + state update ----
    if (tid < 128) {
        int ko_l = tid & 7, b = tid >> 3;
        int ko = bkid * 8 + ko_l;
        int nt = b >> 3, col = b & 7;
        float gsum[4];
        #pragma unroll
        for (int gate = 0; gate < 4; gate++) {
            int m = gate * 8 + ko_l;            // row within block's 32
            int mt2 = m >> 4, ri = m & 15;
            int lane2 = (ri & 7) * 4 + (col >> 1);
            int reg = (ri >> 3) * 2 + (col & 1);
            float ss = 0.f;
            #pragma unroll
            for (int kq2 = 0; kq2 < 4; kq2++)
                ss += red[(((mt2 * 2 + nt) * 4 + kq2) * 32 + lane2) * 4 + reg];
            gsum[gate] = ss;
        }
        float pi, pf, pg, po;
        if (LAYER) {
            pi = bias1[ko]; pf = bias1[512 + ko];
            pg = bias1[1024 + ko]; po = bias1[1536 + ko];
        } else {
            const float* xg = xg0d + ((size_t)(n * Tc + tok) * Bc + b) * H4 + ko;
            pi = xg[0]; pf = xg[512]; pg = xg[1024]; po = xg[1536];
        }
        float gi = gsum[0] + pi, gf = gsum[1] + pf, gg = gsum[2] + pg, go = gsum[3] + po;
        float si = 1.f / (1.f + expf(-gi));
        float sf = 1.f / (1.f + expf(-gf));
        float so = 1.f / (1.f + expf(-go));
        int idx = b * Hc + ko;
        float cn = sf * cst[idx] + si * tanhf(gg);
        float hn = so * tanhf(cn);
        cst[idx]  = cn;
        hout[idx] = hn;
        if (LAYER) {
            g_out1[((size_t)(n * Tc + tok) * Bc + b) * H2 + dir * Hc + ko] = hn;
        } else {
            g_x1[((size_t)tok * Bc + b) * H2 + dir * Hc + ko] = hn;
        }
    }
    gbar(barslot, barnb, sense);
}

__global__ __launch_bounds__(256, 1) void lstm_persist(
    const float* __restrict__ b1f_, const float* __restrict__ b1b_)
{
    extern __shared__ __align__(16) char smemc[];
    uint32_t* hsmH = (uint32_t*)smemc;
    uint32_t* hsmL = hsmH + HS_U32;
    float* red = (float*)(smemc + HS_BYTES);

    int tid = threadIdx.x, bid = blockIdx.x;
    int dir = bid >> 6, bkid = bid & 63;

    const float* bias1 = dir ? b1b_ : b1f_;
    const float* xg0d  = g_xg0 + (size_t)dir * NTB * H4;

    unsigned sdir = 0, sfull = 0;
    int p0 = 0, p1 = 0;

    for (int t = 0; t < Tc; t++) {
        for (int n = 0; n < Nc; n++) {
            int L = t + 1;
            for (int s = 0; s < L; s++) {
                int tok = dir ? (L - 1 - s) : s;
                bool last = (s == L - 1);
                lstm_do_step<0>(tid, dir, bkid, hsmH, hsmL, red,
                                n, tok, p0, bias1, xg0d,
                                last ? 2 : dir, last ? 128u : 64u,
                                last ? sfull : sdir);
                p0 ^= 1;
            }
            for (int s = 0; s < L; s++) {
                int tok = dir ? (L - 1 - s) : s;
                bool last = (s == L - 1);
                lstm_do_step<1>(tid, dir, bkid, hsmH, hsmL, red,
                                n, tok, p1, bias1, xg0d,
                                last ? 2 : dir, last ? 128u : 64u,
                                last ? sfull : sdir);
                p1 ^= 1;
            }
        }
    }

    // fused convA: out1 -> bf16 hi/lo
    for (int i = bid * 256 + tid; i < NTB * H2; i += NBLK * 256) {
        float v = g_out1[i];
        __nv_bfloat16 h = __float2bfloat16(v);
        g_Ahi[i] = h;
        g_Alo[i] = __float2bfloat16(v - __bfloat162float(h));
    }
}

// ================= bf16-split mma.sync FC =================
#define FCBM 128
#define FCBN 128
#define FCBK 64
#define PADK 72
#define FC_SMEM (4 * FCBM * PADK * 2)

__global__ __launch_bounds__(256) void fc_wmma(
    const float* __restrict__ bias, float* __restrict__ out)
{
    extern __shared__ __align__(16) __nv_bfloat16 sm[];
    __nv_bfloat16* sAh = sm;
    __nv_bfloat16* sAl = sm + FCBM * PADK;
    __nv_bfloat16* sBh = sm + 2 * FCBM * PADK;
    __nv_bfloat16* sBl = sm + 3 * FCBM * PADK;

    int tid = threadIdx.x;
    int wid = tid >> 5, lane = tid & 31;
    int g = lane >> 2, q = lane & 3;
    int wm = wid & 3, wn = wid >> 2;
    int bm = blockIdx.y * FCBM, bn = blockIdx.x * FCBN;

    const uint4* A4h = (const uint4*)g_Ahi;
    const uint4* A4l = (const uint4*)g_Alo;
    const uint4* B4h = (const uint4*)g_Bhi;
    const uint4* B4l = (const uint4*)g_Blo;
    const uint4 z4 = make_uint4(0, 0, 0, 0);

    float acc[2][8][4];
    #pragma unroll
    for (int i = 0; i < 2; i++)
        #pragma unroll
        for (int j = 0; j < 8; j++)
            #pragma unroll
            for (int e = 0; e < 4; e++) acc[i][j][e] = 0.f;

    const uint32_t* sA32h = (const uint32_t*)sAh;
    const uint32_t* sA32l = (const uint32_t*)sAl;
    const uint32_t* sB32h = (const uint32_t*)sBh;
    const uint32_t* sB32l = (const uint32_t*)sBl;

    for (int kc = 0; kc < H2 / FCBK; kc++) {
        __syncthreads();
        #pragma unroll
        for (int it = 0; it < 4; it++) {
            int idx = tid + it * 256;
            int m = idx >> 3, kg = idx & 7;
            int gm = bm + m;
            size_t gi = (size_t)gm * (H2 / 8) + kc * 8 + kg;
            uint4 vh = z4, vl = z4;
            if (gm < NTB) { vh = A4h[gi]; vl = A4l[gi]; }
            *(uint4*)&sAh[m * PADK + kg * 8] = vh;
            *(uint4*)&sAl[m * PADK + kg * 8] = vl;
        }
        #pragma unroll
        for (int it = 0; it < 4; it++) {
            int idx = tid + it * 256;
            int n = idx >> 3, kg = idx & 7;
            int gn = bn + n;
            uint4 vh = z4, vl = z4;
            if (gn < Vc) {
                size_t gi = (size_t)gn * (H2 / 8) + kc * 8 + kg;
                vh = B4h[gi]; vl = B4l[gi];
            }
            *(uint4*)&sBh[n * PADK + kg * 8] = vh;
            *(uint4*)&sBl[n * PADK + kg * 8] = vl;
        }
        __syncthreads();

        #pragma unroll
        for (int ks = 0; ks < 4; ks++) {
            uint32_t ah[2][4], al[2][4];
            #pragma unroll
            for (int mi = 0; mi < 2; mi++) {
                int r0 = (wm * 32 + mi * 16 + g) * (PADK / 2);
                int r8 = r0 + 8 * (PADK / 2);
                int w0 = ks * 8 + q, w4 = w0 + 4;
                ah[mi][0] = sA32h[r0 + w0]; ah[mi][1] = sA32h[r8 + w0];
                ah[mi][2] = sA32h[r0 + w4]; ah[mi][3] = sA32h[r8 + w4];
                al[mi][0] = sA32l[r0 + w0]; al[mi][1] = sA32l[r8 + w0];
                al[mi][2] = sA32l[r0 + w4]; al[mi][3] = sA32l[r8 + w4];
            }
            #pragma unroll
            for (int ni = 0; ni < 8; ni++) {
                int nr = (wn * 64 + ni * 8 + g) * (PADK / 2);
                int w0 = ks * 8 + q, w4 = w0 + 4;
                uint32_t bh0 = sB32h[nr + w0], bh1 = sB32h[nr + w4];
                uint32_t bl0 = sB32l[nr + w0], bl1 = sB32l[nr + w4];
                #pragma unroll
                for (int mi = 0; mi < 2; mi++) {
                    float* c = acc[mi][ni];
                    mma16816(c[0], c[1], c[2], c[3],
                             ah[mi][0], ah[mi][1], ah[mi][2], ah[mi][3], bh0, bh1);
                    mma16816(c[0], c[1], c[2], c[3],
                             al[mi][0], al[mi][1], al[mi][2], al[mi][3], bh0, bh1);
                    mma16816(c[0], c[1], c[2], c[3],
                             ah[mi][0], ah[mi][1], ah[mi][2], ah[mi][3], bl0, bl1);
                }
            }
        }
    }

    #pragma unroll
    for (int mi = 0; mi < 2; mi++) {
        int row0 = bm + wm * 32 + mi * 16 + g;
        int row1 = row0 + 8;
        #pragma unroll
        for (int ni = 0; ni < 8; ni++) {
            int col = bn + wn * 64 + ni * 8 + q * 2;
            if (col >= Vc) continue;
            float b0 = bias[col], b1 = bias[col + 1];
            const float* c = acc[mi][ni];
            if (row0 < NTB) {
                float2 v = make_float2(c[0] + b0, c[1] + b1);
                *(float2*)&out[(size_t)row0 * Vc + col] = v;
            }
            if (row1 < NTB) {
                float2 v = make_float2(c[2] + b0, c[3] + b1);
                *(float2*)&out[(size_t)row1 * Vc + col] = v;
            }
        }
    }
}

// ---------------- host ----------------
extern "C" void kernel_launch(void* const* d_in, const int* in_sizes, int n_in,
                              void* d_out, int out_size)
{
    const float* img   = (const float*)d_in[0];
    const int*   caps  = (const int*)  d_in[1];
    const float* Wh1   = (const float*)d_in[2];
    const float* bh1   = (const float*)d_in[3];
    const float* Wh2   = (const float*)d_in[4];
    const float* bh2   = (const float*)d_in[5];
    const float* Wc1   = (const float*)d_in[6];
    const float* bc1   = (const float*)d_in[7];
    const float* Wc2   = (const float*)d_in[8];
    const float* bc2   = (const float*)d_in[9];
    const float* emb   = (const float*)d_in[10];
    const float* Wih0f = (const float*)d_in[11];
    const float* Whh0f = (const float*)d_in[12];
    const float* b0f   = (const float*)d_in[13];
    const float* Wih0b = (const float*)d_in[14];
    const float* Whh0b = (const float*)d_in[15];
    const float* b0b   = (const float*)d_in[16];
    const float* Wih1f = (const float*)d_in[17];
    const float* Whh1f = (const float*)d_in[18];
    const float* b1f   = (const float*)d_in[19];
    const float* Wih1b = (const float*)d_in[20];
    const float* Whh1b = (const float*)d_in[21];
    const float* b1b   = (const float*)d_in[22];
    const float* Wfc   = (const float*)d_in[23];
    const float* bfc   = (const float*)d_in[24];
    float* outp = (float*)d_out;

    float *p_W0T, *p_W1T;
    cudaGetSymbolAddress((void**)&p_W0T,  g_W0T);
    cudaGetSymbolAddress((void**)&p_W1T,  g_W1T);

    const size_t W1ROW = (size_t)H4 * (Hc + H2);

    // Launch 0: transposes + MLP stage1 + gather + convB
    TParams6 tp;
    tp.p[0] = { Whh0f, p_W0T,                 Hc, Hc };
    tp.p[1] = { Whh0b, p_W0T + (size_t)H4*Hc, Hc, Hc };
    tp.p[2] = { Whh1f, p_W1T,                 Hc, Hc + H2 };
    tp.p[3] = { Wih1f, p_W1T + Hc,            H2, Hc + H2 };
    tp.p[4] = { Whh1b, p_W1T + W1ROW,         Hc, Hc + H2 };
    tp.p[5] = { Wih1b, p_W1T + W1ROW + Hc,    H2, Hc + H2 };
    pre1<<<P1_TOTAL, 256>>>(tp, img, Wh1, bh1, Wc1, bc1, caps, emb, Wfc);

    // Launch 1: fragment-linear split-bf16 recurrent weights
    wfrag<<<(262144 + 786432) / 256, 256>>>();

    // Launch 2: MLP stage2 (dual)
    pre2k<<<dim3(Hc/64, 1, 2), 256>>>(Wh2, bh2, Wc2, bc2);

    // Launch 3: xg0 GEMMs (z=0,1) + b-major state broadcast (z=2)
    pre3<<<dim3(H4/128, (NTB+127)/128, 3), 256>>>(Wih0f, b0f, Wih0b, b0b);

    // Launch 4: persistent recurrent chain (tensor-core stage B) + fused convA
    cudaFuncSetAttribute(lstm_persist, cudaFuncAttributeMaxDynamicSharedMemorySize, LSTM_SMEM);
    lstm_persist<<<NBLK, 256, LSTM_SMEM>>>(b1f, b1b);

    // Launch 5: tensor-core FC
    cudaFuncSetAttribute(fc_wmma, cudaFuncAttributeMaxDynamicSharedMemorySize, FC_SMEM);
    fc_wmma<<<dim3((Vc + FCBN - 1)/FCBN, (NTB + FCBM - 1)/FCBM), 256, FC_SMEM>>>(bfc, outp);
}

// round 17
// speedup vs baseline: 1.4134x; 1.0999x over previous
#include <cuda_runtime.h>
#include <cuda_bf16.h>
#include <math.h>
#include <stdint.h>

// Problem constants
#define Bc 16
#define Nc 5
#define Tc 10
#define Hc 512
#define Ec 250
#define Vc 30000
#define Fc 2048
#define H4 2048
#define H2 1024
#define NTB (Nc*Tc*Bc)   // 800
#define NBLK 128
#define HPAD 772         // hsm row stride in uint32

// packed fp32x2 FMA (SASS FFMA2) — fp32 GEMMs
#define FMA2(d, a, b) asm("fma.rn.f32x2 %0, %1, %2, %0;" : "+l"(d) : "l"(a), "l"(b))

__device__ __forceinline__ float f2lo(unsigned long long v) { return __uint_as_float((unsigned)v); }
__device__ __forceinline__ float f2hi(unsigned long long v) { return __uint_as_float((unsigned)(v >> 32)); }

// pack two f32 -> bf16x2 (lo in lower half, hi in upper half)
__device__ __forceinline__ uint32_t pkbf(float lo, float hi) {
    uint32_t r;
    asm("cvt.rn.bf16x2.f32 %0, %1, %2;" : "=r"(r) : "f"(hi), "f"(lo));
    return r;
}

// ---------------- device scratch ----------------
__device__ __align__(16) float g_tmp[Bc*H2];
__device__ __align__(16) float g_tmp2[Bc*H2];
__device__ __align__(16) float g_h0[Bc*Hc];
__device__ __align__(16) float g_c0[Bc*Hc];
__device__ __align__(16) float g_hst[4][2][Bc*Hc];   // state h, b-major
__device__ __align__(16) float g_cst[4][Bc*Hc];      // state c, b-major
__device__ __align__(16) float g_x0[NTB*Ec];
__device__ __align__(16) float g_xg0[2*NTB*H4];
__device__ __align__(16) float g_x1[Tc*Bc*H2];       // [t][b][1024]
__device__ __align__(16) float g_out1[NTB*H2];
__device__ __align__(16) float g_W0T[2*H4*Hc];
__device__ __align__(16) float g_W1T[2*H4*(Hc+H2)];
// fragment-linear split-bf16 weights
#define W0F_DIR 262144
#define W1F_DIR 786432
__device__ __align__(16) uint4 g_W0F[2*W0F_DIR];
__device__ __align__(16) uint4 g_W1F[2*W1F_DIR];
__device__ __align__(16) __nv_bfloat16 g_Ahi[NTB*H2];
__device__ __align__(16) __nv_bfloat16 g_Alo[NTB*H2];
__device__ __align__(16) __nv_bfloat16 g_Bhi[(size_t)Vc*H2];
__device__ __align__(16) __nv_bfloat16 g_Blo[(size_t)Vc*H2];

// barrier state
__device__ __align__(128) unsigned g_cnt[96];
__device__ __align__(128) unsigned g_sns[96];

// ---------------- shared sgemm body ----------------
struct TParam { const float* in; float* out; int R; int ostride; };
struct TParams6 { TParam p[6]; };

__device__ __forceinline__ void sgemm_body(
    const float* A, const float* W, const float* bias, float* C,
    int M, int N, int K, int relu, int bm, int bn, int tid,
    float* As, float* Bs)
{
    int tm = (tid >> 4) << 2;
    int tn = (tid & 15) << 2;
    float acc[4][4] = {};
    for (int k0 = 0; k0 < K; k0 += 16) {
        #pragma unroll
        for (int e = 0; e < 4; e++) {
            int idx = tid + e * 256;
            int r = idx >> 4, c = idx & 15;
            int gr = bm + r, gc = k0 + c;
            As[c * 64 + r] = (gr < M && gc < K) ? A[(size_t)gr * K + gc] : 0.f;
        }
        #pragma unroll
        for (int e = 0; e < 4; e++) {
            int idx = tid + e * 256;
            int r = idx >> 6, c = idx & 63;
            int gr = k0 + r, gc = bn + c;
            Bs[r * 64 + c] = (gr < K && gc < N) ? W[(size_t)gr * N + gc] : 0.f;
        }
        __syncthreads();
        #pragma unroll
        for (int kk = 0; kk < 16; kk++) {
            float4 a4 = *(const float4*)&As[kk * 64 + tm];
            float4 b4 = *(const float4*)&Bs[kk * 64 + tn];
            float a[4] = {a4.x, a4.y, a4.z, a4.w};
            float b[4] = {b4.x, b4.y, b4.z, b4.w};
            #pragma unroll
            for (int i = 0; i < 4; i++)
                #pragma unroll
                for (int j = 0; j < 4; j++)
                    acc[i][j] = fmaf(a[i], b[j], acc[i][j]);
        }
        __syncthreads();
    }
    #pragma unroll
    for (int i = 0; i < 4; i++) {
        int gm = bm + tm + i;
        if (gm >= M) continue;
        #pragma unroll
        for (int j = 0; j < 4; j++) {
            int gn = bn + tn + j;
            if (gn >= N) continue;
            float v = acc[i][j] + bias[gn];
            if (relu) v = fmaxf(v, 0.f);
            C[(size_t)gm * N + gn] = v;
        }
    }
}

// ================= pre1 =================
#define P1_TRANS 12288
#define P1_MLP   (P1_TRANS + 32)
#define P1_GATH  (P1_MLP + 800)
#define P1_TOTAL (P1_GATH + 30016)

__global__ __launch_bounds__(256) void pre1(
    TParams6 tp,
    const float* __restrict__ img,
    const float* __restrict__ Wh1, const float* __restrict__ bh1,
    const float* __restrict__ Wc1, const float* __restrict__ bc1,
    const int* __restrict__ caps, const float* __restrict__ emb,
    const float* __restrict__ Wfc)
{
    __shared__ float sh[2048];
    int id = blockIdx.x, tid = threadIdx.x;
    int tx = tid & 31, ty = tid >> 5;

    if (id < P1_TRANS) {
        int which = id / 2048, rem = id % 2048;
        int bx = rem & 63, by = rem >> 6;
        TParam p = tp.p[which];
        int c0 = bx * 32, r0 = by * 32;
        if (r0 >= p.R) return;
        for (int j = ty; j < 32; j += 8) {
            int r = r0 + j, c = c0 + tx;
            sh[j * 33 + tx] = (r < p.R) ? p.in[(size_t)r * H4 + c] : 0.f;
        }
        __syncthreads();
        for (int j = ty; j < 32; j += 8) {
            int c = c0 + j, r = r0 + tx;
            if (r < p.R) p.out[(size_t)c * p.ostride + r] = sh[tx * 33 + j];
        }
    } else if (id < P1_MLP) {
        int sub = id - P1_TRANS;
        int z = sub >> 4, bx = sub & 15;
        sgemm_body(img, z ? Wc1 : Wh1, z ? bc1 : bh1, z ? g_tmp2 : g_tmp,
                   Bc, H2, Fc, 1, 0, bx * 64, tid, sh, sh + 1024);
    } else if (id < P1_GATH) {
        int rid = id - P1_MLP;
        int b = rid & 15;
        int nt = rid >> 4;
        int n = nt / Tc, t = nt % Tc;
        int tok = caps[b * (Nc * Tc) + n * Tc + t];
        const float* e = emb + (size_t)tok * Ec;
        float* o = g_x0 + (size_t)rid * Ec;
        for (int i = tid; i < Ec; i += 256) o[i] = e[i];
    } else {
        int sub = id - P1_GATH;
        int n0 = (sub % 938) * 32, k0 = (sub / 938) * 32;
        for (int j = ty; j < 32; j += 8) {
            int k = k0 + j, n = n0 + tx;
            sh[j * 33 + tx] = (n < Vc) ? Wfc[(size_t)k * Vc + n] : 0.f;
        }
        __syncthreads();
        for (int j = ty; j < 32; j += 8) {
            int n = n0 + j, k = k0 + tx;
            if (n < Vc) {
                float v = sh[tx * 33 + j];
                __nv_bfloat16 h = __float2bfloat16(v);
                g_Bhi[(size_t)n * H2 + k] = h;
                g_Blo[(size_t)n * H2 + k] = __float2bfloat16(v - __bfloat162float(h));
            }
        }
    }
}

// ================= wfrag =================
__global__ __launch_bounds__(256) void wfrag()
{
    int u = blockIdx.x * 256 + threadIdx.x;
    int layer = (u >= 262144);
    if (layer) u -= 262144;
    const int KS = layer ? 24 : 8;
    const int K  = layer ? (Hc + H2) : Hc;
    int lane = u & 31;
    int mt = (u >> 5) & 1;
    int rest = u >> 6;
    int ks = rest % KS; rest /= KS;
    int kq = rest & 3;  rest >>= 2;
    int bkid = rest & 63;
    int dir = rest >> 6;
    int g = lane >> 2, q = lane & 3;

    const float* WT = layer ? (g_W1T + (size_t)dir * H4 * (Hc + H2))
                            : (g_W0T + (size_t)dir * H4 * Hc);
    int kk = (kq * KS + ks) * 16;
    int r0 = mt * 1024 + bkid * 8 + g;
    int r1 = r0 + 512;
    float2 w0 = *(const float2*)&WT[(size_t)r0 * K + kk + 2 * q];
    float2 w1 = *(const float2*)&WT[(size_t)r1 * K + kk + 2 * q];
    float2 w2 = *(const float2*)&WT[(size_t)r0 * K + kk + 2 * q + 8];
    float2 w3 = *(const float2*)&WT[(size_t)r1 * K + kk + 2 * q + 8];

    uint4 hi, lo;
    hi.x = pkbf(w0.x, w0.y);
    hi.y = pkbf(w1.x, w1.y);
    hi.z = pkbf(w2.x, w2.y);
    hi.w = pkbf(w3.x, w3.y);
    lo.x = pkbf(w0.x - __uint_as_float(hi.x << 16), w0.y - __uint_as_float(hi.x & 0xFFFF0000u));
    lo.y = pkbf(w1.x - __uint_as_float(hi.y << 16), w1.y - __uint_as_float(hi.y & 0xFFFF0000u));
    lo.z = pkbf(w2.x - __uint_as_float(hi.z << 16), w2.y - __uint_as_float(hi.z & 0xFFFF0000u));
    lo.w = pkbf(w3.x - __uint_as_float(hi.w << 16), w3.y - __uint_as_float(hi.w & 0xFFFF0000u));

    uint4* dst = (layer ? g_W1F : g_W0F)
               + (size_t)dir * (layer ? W1F_DIR : W0F_DIR)
               + ((size_t)((bkid * 4 + kq) * KS + ks) * 4 + mt * 2) * 32 + lane;
    dst[0]  = hi;
    dst[32] = lo;
}

// ================= pre2 =================
__global__ __launch_bounds__(256) void pre2k(
    const float* __restrict__ Wh2, const float* __restrict__ bh2,
    const float* __restrict__ Wc2, const float* __restrict__ bc2)
{
    __shared__ float sh[2048];
    int z = blockIdx.z;
    sgemm_body(z ? g_tmp2 : g_tmp, z ? Wc2 : Wh2, z ? bc2 : bh2, z ? g_c0 : g_h0,
               Bc, Hc, H2, 1, 0, blockIdx.x * 64, threadIdx.x, sh, sh + 1024);
}

// ================= pre3 =================
__global__ __launch_bounds__(256) void pre3(
    const float* __restrict__ B0, const float* __restrict__ bias0,
    const float* __restrict__ B1, const float* __restrict__ bias1)
{
    __shared__ __align__(16) float As[2][16][128];
    __shared__ __align__(16) float Bs[2][16][256];

    if (blockIdx.z == 2) {
        int lin = blockIdx.y * 16 + blockIdx.x;
        if (lin < 32) {
            int i = lin * 256 + threadIdx.x;
            float h = g_h0[i];
            float c = g_c0[i];
            #pragma unroll
            for (int s = 0; s < 4; s++) {
                g_hst[s][0][i] = h;
                g_cst[s][i]    = c;
            }
        }
        return;
    }

    const float* A = g_x0;
    const float* B = blockIdx.z ? B1 : B0;
    const float* bias = blockIdx.z ? bias1 : bias0;
    float* C = blockIdx.z ? (g_xg0 + (size_t)NTB * H4) : g_xg0;
    const int M = NTB, N = H4, K = Ec;

    int tid = threadIdx.x;
    int bm = blockIdx.y * 128, bn = blockIdx.x * 128;
    int tx = tid & 15, ty = tid >> 4;
    int ar = tid >> 2, ac = (tid & 3) * 4;
    int br = tid >> 5, bc = (tid & 31) * 4;

    unsigned long long acc[4][8];
    #pragma unroll
    for (int i = 0; i < 4; i++)
        #pragma unroll
        for (int j = 0; j < 8; j++) acc[i][j] = 0ull;

    float a0[4], a1[4], b0[4], b1[4];
    int KT = (K + 15) / 16;

#define LOADTILE(KT_) do {                                                        \
    int k0 = (KT_) * 16;                                                          \
    int gr0 = bm + ar, gr1 = bm + ar + 64;                                        \
    _Pragma("unroll") for (int j = 0; j < 4; j++) {                               \
        int gk = k0 + ac + j;                                                     \
        bool ok = (gk < K);                                                       \
        a0[j] = (ok && gr0 < M) ? A[(size_t)gr0 * K + gk] : 0.f;                  \
        a1[j] = (ok && gr1 < M) ? A[(size_t)gr1 * K + gk] : 0.f;                  \
    }                                                                             \
    int gk0 = k0 + br, gk1 = k0 + br + 8;                                         \
    _Pragma("unroll") for (int j = 0; j < 4; j++) {                               \
        int gc = bn + bc + j;                                                     \
        b0[j] = (gk0 < K) ? B[(size_t)gk0 * N + gc] : 0.f;                        \
        b1[j] = (gk1 < K) ? B[(size_t)gk1 * N + gc] : 0.f;                        \
    }                                                                             \
} while (0)

#define STORETILE(BUF_) do {                                                      \
    _Pragma("unroll") for (int j = 0; j < 4; j++) {                               \
        As[BUF_][ac + j][ar]      = a0[j];                                        \
        As[BUF_][ac + j][ar + 64] = a1[j];                                        \
        Bs[BUF_][br][(bc + j) * 2]         = b0[j];                               \
        Bs[BUF_][br][(bc + j) * 2 + 1]     = b0[j];                               \
        Bs[BUF_][br + 8][(bc + j) * 2]     = b1[j];                               \
        Bs[BUF_][br + 8][(bc + j) * 2 + 1] = b1[j];                               \
    }                                                                             \
} while (0)

    LOADTILE(0);
    STORETILE(0);
    __syncthreads();

    for (int kt = 0; kt < KT; kt++) {
        int cur = kt & 1;
        if (kt + 1 < KT) LOADTILE(kt + 1);
        #pragma unroll
        for (int k = 0; k < 16; k++) {
            unsigned long long a2[4], b2[8];
            #pragma unroll
            for (int i = 0; i < 4; i++)
                a2[i] = *(const unsigned long long*)&As[cur][k][ty * 8 + 2 * i];
            #pragma unroll
            for (int j = 0; j < 8; j++)
                b2[j] = *(const unsigned long long*)&Bs[cur][k][(tx + 16 * j) * 2];
            #pragma unroll
            for (int i = 0; i < 4; i++)
                #pragma unroll
                for (int j = 0; j < 8; j++)
                    FMA2(acc[i][j], a2[i], b2[j]);
        }
        if (kt + 1 < KT) STORETILE(cur ^ 1);
        __syncthreads();
    }

    #pragma unroll
    for (int j = 0; j < 8; j++) {
        int col = bn + tx + 16 * j;
        float bb = bias[col];
        #pragma unroll
        for (int i = 0; i < 4; i++) {
            int r0 = bm + ty * 8 + 2 * i;
            float lo = f2lo(acc[i][j]) + bb;
            float hi = f2hi(acc[i][j]) + bb;
            if (r0 < M)     C[(size_t)r0 * N + col] = lo;
            if (r0 + 1 < M) C[(size_t)(r0 + 1) * N + col] = hi;
        }
    }
#undef LOADTILE
#undef STORETILE
}

// ================= mma.sync helper =================
__device__ __forceinline__ void mma16816(
    float& c0, float& c1, float& c2, float& c3,
    uint32_t a0, uint32_t a1, uint32_t a2, uint32_t a3,
    uint32_t b0, uint32_t b1)
{
    asm volatile(
        "mma.sync.aligned.m16n8k16.row.col.f32.bf16.bf16.f32 "
        "{%0,%1,%2,%3}, {%4,%5,%6,%7}, {%8,%9}, {%0,%1,%2,%3};"
        : "+f"(c0), "+f"(c1), "+f"(c2), "+f"(c3)
        : "r"(a0), "r"(a1), "r"(a2), "r"(a3), "r"(b0), "r"(b1));
}

// ================= persistent recurrent kernel (TC stage B, 16 warps) =================
__device__ __forceinline__ void gbar(int slot, unsigned nb, unsigned& sense)
{
    __syncthreads();
    sense ^= 1;
    if (threadIdx.x == 0) {
        unsigned* c = &g_cnt[slot * 32];
        unsigned* s = &g_sns[slot * 32];
        __threadfence();
        unsigned old = atomicAdd(c, 1);
        if (old == nb - 1) {
            *c = 0;
            __threadfence();
            atomicExch(s, sense);
        } else {
            while (*(volatile unsigned*)s != sense) __nanosleep(32);
        }
        __threadfence();
    }
    __syncthreads();
}

#define HS_U32   (16 * HPAD)
#define HS_BYTES (HS_U32 * 4 * 2)          // 98816
#define RED_FLOATS 4096                    // 2mt*2nt*8kq*32lane*4
#define LSTM_SMEM (HS_BYTES + RED_FLOATS * 4)   // 115200
#define LTH 512

template<int LAYER>
__device__ __forceinline__ void lstm_do_step(
    int tid, int dir, int bkid,
    uint32_t* hsmH, uint32_t* hsmL, float* red,
    int n, int tok, int par,
    const float* bias1, const float* xg0d,
    int barslot, unsigned barnb, unsigned& sense)
{
    const int K    = LAYER ? (Hc + H2) : Hc;
    const int KTOT = LAYER ? 96 : 32;      // total k16 chunks
    const int KSW  = KTOT / 8;             // per-warp chunks (12 or 4)
    const int Q    = K / 4;
    int slot = LAYER ? (2 + dir) : dir;
    const float* hglob = &g_hst[slot][par][0];
    float* hout = &g_hst[slot][par ^ 1][0];
    float* cst  = &g_cst[slot][0];

    // ---- stage A ----
    {
        const float* x1g = g_x1 + (size_t)tok * Bc * H2;
        for (int idx = tid; idx < 4 * K; idx += LTH) {
            int b = idx / Q, k4 = idx % Q;
            int k = k4 * 4;
            float4 v;
            if (!LAYER || k < Hc) v = *(const float4*)&hglob[b * Hc + k];
            else                  v = *(const float4*)&x1g[b * H2 + (k - Hc)];
            uint32_t h01 = pkbf(v.x, v.y), h23 = pkbf(v.z, v.w);
            float r0 = v.x - __uint_as_float(h01 << 16);
            float r1 = v.y - __uint_as_float(h01 & 0xFFFF0000u);
            float r2 = v.z - __uint_as_float(h23 << 16);
            float r3 = v.w - __uint_as_float(h23 & 0xFFFF0000u);
            int off = b * HPAD + k4 * 2;
            *(uint2*)&hsmH[off] = make_uint2(h01, h23);
            *(uint2*)&hsmL[off] = make_uint2(pkbf(r0, r1), pkbf(r2, r3));
        }
    }
    __syncthreads();

    // ---- stage B: warp = (mt, kq 0..7) ----
    int wid = tid >> 5, lane = tid & 31;
    int mt = wid & 1, kq = wid >> 1;
    int g = lane >> 2, q = lane & 3;
    const uint4* WF = (LAYER ? g_W1F : g_W0F)
                    + (size_t)dir * (LAYER ? W1F_DIR : W0F_DIR)
                    + ((size_t)bkid * KTOT + kq * KSW) * 128 + mt * 64 + lane;
    float c[2][4] = {};
    for (int ks = 0; ks < KSW; ks++) {
        const uint4* pa = WF + ks * 128;
        uint4 AH = pa[0];
        uint4 AL = pa[32];
        int kp = (kq * KSW + ks) * 8 + q;
        #pragma unroll
        for (int nt = 0; nt < 2; nt++) {
            int rb = (nt * 8 + g) * HPAD + kp;
            uint32_t bh0 = hsmH[rb], bh1 = hsmH[rb + 4];
            uint32_t bl0 = hsmL[rb], bl1 = hsmL[rb + 4];
            mma16816(c[nt][0], c[nt][1], c[nt][2], c[nt][3],
                     AH.x, AH.y, AH.z, AH.w, bh0, bh1);
            mma16816(c[nt][0], c[nt][1], c[nt][2], c[nt][3],
                     AL.x, AL.y, AL.z, AL.w, bh0, bh1);
            mma16816(c[nt][0], c[nt][1], c[nt][2], c[nt][3],
                     AH.x, AH.y, AH.z, AH.w, bl0, bl1);
        }
    }

    // ---- stage C: dump partials ----
    #pragma unroll
    for (int nt = 0; nt < 2; nt++) {
        *(float4*)&red[(((mt * 2 + nt) * 8 + kq) * 32 + lane) * 4] =
            make_float4(c[nt][0], c[nt][1], c[nt][2], c[nt][3]);
    }
    __syncthreads();

    // ---- stage D ----
    if (tid < 128) {
        int ko_l = tid & 7, b = tid >> 3;
        int ko = bkid * 8 + ko_l;
        int nt = b >> 3, col = b & 7;
        float gsum[4];
        #pragma unroll
        for (int gate = 0; gate < 4; gate++) {
            int m = gate * 8 + ko_l;
            int mt2 = m >> 4, ri = m & 15;
            int lane2 = (ri & 7) * 4 + (col >> 1);
            int reg = (ri >> 3) * 2 + (col & 1);
            float ss = 0.f;
            #pragma unroll
            for (int kq2 = 0; kq2 < 8; kq2++)
                ss += red[(((mt2 * 2 + nt) * 8 + kq2) * 32 + lane2) * 4 + reg];
            gsum[gate] = ss;
        }
        float pi, pf, pg, po;
        if (LAYER) {
            pi = bias1[ko]; pf = bias1[512 + ko];
            pg = bias1[1024 + ko]; po = bias1[1536 + ko];
        } else {
            const float* xg = xg0d + ((size_t)(n * Tc + tok) * Bc + b) * H4 + ko;
            pi = xg[0]; pf = xg[512]; pg = xg[1024]; po = xg[1536];
        }
        float gi = gsum[0] + pi, gf = gsum[1] + pf, gg = gsum[2] + pg, go = gsum[3] + po;
        float si = 1.f / (1.f + expf(-gi));
        float sf = 1.f / (1.f + expf(-gf));
        float so = 1.f / (1.f + expf(-go));
        int idx = b * Hc + ko;
        float cn = sf * cst[idx] + si * tanhf(gg);
        float hn = so * tanhf(cn);
        cst[idx]  = cn;
        hout[idx] = hn;
        if (LAYER) {
            g_out1[((size_t)(n * Tc + tok) * Bc + b) * H2 + dir * Hc + ko] = hn;
        } else {
            g_x1[((size_t)tok * Bc + b) * H2 + dir * Hc + ko] = hn;
        }
    }
    gbar(barslot, barnb, sense);
}

__global__ __launch_bounds__(LTH, 1) void lstm_persist(
    const float* __restrict__ b1f_, const float* __restrict__ b1b_)
{
    extern __shared__ __align__(16) char smemc[];
    uint32_t* hsmH = (uint32_t*)smemc;
    uint32_t* hsmL = hsmH + HS_U32;
    float* red = (float*)(smemc + HS_BYTES);

    int tid = threadIdx.x, bid = blockIdx.x;
    int dir = bid >> 6, bkid = bid & 63;

    const float* bias1 = dir ? b1b_ : b1f_;
    const float* xg0d  = g_xg0 + (size_t)dir * NTB * H4;

    unsigned sdir = 0, sfull = 0;
    int p0 = 0, p1 = 0;

    for (int t = 0; t < Tc; t++) {
        for (int n = 0; n < Nc; n++) {
            int L = t + 1;
            for (int s = 0; s < L; s++) {
                int tok = dir ? (L - 1 - s) : s;
                bool last = (s == L - 1);
                lstm_do_step<0>(tid, dir, bkid, hsmH, hsmL, red,
                                n, tok, p0, bias1, xg0d,
                                last ? 2 : dir, last ? 128u : 64u,
                                last ? sfull : sdir);
                p0 ^= 1;
            }
            for (int s = 0; s < L; s++) {
                int tok = dir ? (L - 1 - s) : s;
                bool last = (s == L - 1);
                lstm_do_step<1>(tid, dir, bkid, hsmH, hsmL, red,
                                n, tok, p1, bias1, xg0d,
                                last ? 2 : dir, last ? 128u : 64u,
                                last ? sfull : sdir);
                p1 ^= 1;
            }
        }
    }

    // fused convA
    for (int i = bid * LTH + tid; i < NTB * H2; i += NBLK * LTH) {
        float v = g_out1[i];
        __nv_bfloat16 h = __float2bfloat16(v);
        g_Ahi[i] = h;
        g_Alo[i] = __float2bfloat16(v - __bfloat162float(h));
    }
}

// ================= bf16-split mma.sync FC =================
#define FCBM 128
#define FCBN 128
#define FCBK 64
#define PADK 72
#define FC_SMEM (4 * FCBM * PADK * 2)

__global__ __launch_bounds__(256) void fc_wmma(
    const float* __restrict__ bias, float* __restrict__ out)
{
    extern __shared__ __align__(16) __nv_bfloat16 sm[];
    __nv_bfloat16* sAh = sm;
    __nv_bfloat16* sAl = sm + FCBM * PADK;
    __nv_bfloat16* sBh = sm + 2 * FCBM * PADK;
    __nv_bfloat16* sBl = sm + 3 * FCBM * PADK;

    int tid = threadIdx.x;
    int wid = tid >> 5, lane = tid & 31;
    int g = lane >> 2, q = lane & 3;
    int wm = wid & 3, wn = wid >> 2;
    int bm = blockIdx.y * FCBM, bn = blockIdx.x * FCBN;

    const uint4* A4h = (const uint4*)g_Ahi;
    const uint4* A4l = (const uint4*)g_Alo;
    const uint4* B4h = (const uint4*)g_Bhi;
    const uint4* B4l = (const uint4*)g_Blo;
    const uint4 z4 = make_uint4(0, 0, 0, 0);

    float acc[2][8][4];
    #pragma unroll
    for (int i = 0; i < 2; i++)
        #pragma unroll
        for (int j = 0; j < 8; j++)
            #pragma unroll
            for (int e = 0; e < 4; e++) acc[i][j][e] = 0.f;

    const uint32_t* sA32h = (const uint32_t*)sAh;
    const uint32_t* sA32l = (const uint32_t*)sAl;
    const uint32_t* sB32h = (const uint32_t*)sBh;
    const uint32_t* sB32l = (const uint32_t*)sBl;

    for (int kc = 0; kc < H2 / FCBK; kc++) {
        __syncthreads();
        #pragma unroll
        for (int it = 0; it < 4; it++) {
            int idx = tid + it * 256;
            int m = idx >> 3, kg = idx & 7;
            int gm = bm + m;
            size_t gi = (size_t)gm * (H2 / 8) + kc * 8 + kg;
            uint4 vh = z4, vl = z4;
            if (gm < NTB) { vh = A4h[gi]; vl = A4l[gi]; }
            *(uint4*)&sAh[m * PADK + kg * 8] = vh;
            *(uint4*)&sAl[m * PADK + kg * 8] = vl;
        }
        #pragma unroll
        for (int it = 0; it < 4; it++) {
            int idx = tid + it * 256;
            int n = idx >> 3, kg = idx & 7;
            int gn = bn + n;
            uint4 vh = z4, vl = z4;
            if (gn < Vc) {
                size_t gi = (size_t)gn * (H2 / 8) + kc * 8 + kg;
                vh = B4h[gi]; vl = B4l[gi];
            }
            *(uint4*)&sBh[n * PADK + kg * 8] = vh;
            *(uint4*)&sBl[n * PADK + kg * 8] = vl;
        }
        __syncthreads();

        #pragma unroll
        for (int ks = 0; ks < 4; ks++) {
            uint32_t ah[2][4], al[2][4];
            #pragma unroll
            for (int mi = 0; mi < 2; mi++) {
                int r0 = (wm * 32 + mi * 16 + g) * (PADK / 2);
                int r8 = r0 + 8 * (PADK / 2);
                int w0 = ks * 8 + q, w4 = w0 + 4;
                ah[mi][0] = sA32h[r0 + w0]; ah[mi][1] = sA32h[r8 + w0];
                ah[mi][2] = sA32h[r0 + w4]; ah[mi][3] = sA32h[r8 + w4];
                al[mi][0] = sA32l[r0 + w0]; al[mi][1] = sA32l[r8 + w0];
                al[mi][2] = sA32l[r0 + w4]; al[mi][3] = sA32l[r8 + w4];
            }
            #pragma unroll
            for (int ni = 0; ni < 8; ni++) {
                int nr = (wn * 64 + ni * 8 + g) * (PADK / 2);
                int w0 = ks * 8 + q, w4 = w0 + 4;
                uint32_t bh0 = sB32h[nr + w0], bh1 = sB32h[nr + w4];
                uint32_t bl0 = sB32l[nr + w0], bl1 = sB32l[nr + w4];
                #pragma unroll
                for (int mi = 0; mi < 2; mi++) {
                    float* c = acc[mi][ni];
                    mma16816(c[0], c[1], c[2], c[3],
                             ah[mi][0], ah[mi][1], ah[mi][2], ah[mi][3], bh0, bh1);
                    mma16816(c[0], c[1], c[2], c[3],
                             al[mi][0], al[mi][1], al[mi][2], al[mi][3], bh0, bh1);
                    mma16816(c[0], c[1], c[2], c[3],
                             ah[mi][0], ah[mi][1], ah[mi][2], ah[mi][3], bl0, bl1);
                }
            }
        }
    }

    #pragma unroll
    for (int mi = 0; mi < 2; mi++) {
        int row0 = bm + wm * 32 + mi * 16 + g;
        int row1 = row0 + 8;
        #pragma unroll
        for (int ni = 0; ni < 8; ni++) {
            int col = bn + wn * 64 + ni * 8 + q * 2;
            if (col >= Vc) continue;
            float b0 = bias[col], b1 = bias[col + 1];
            const float* c = acc[mi][ni];
            if (row0 < NTB) {
                float2 v = make_float2(c[0] + b0, c[1] + b1);
                *(float2*)&out[(size_t)row0 * Vc + col] = v;
            }
            if (row1 < NTB) {
                float2 v = make_float2(c[2] + b0, c[3] + b1);
                *(float2*)&out[(size_t)row1 * Vc + col] = v;
            }
        }
    }
}

// ---------------- host ----------------
extern "C" void kernel_launch(void* const* d_in, const int* in_sizes, int n_in,
                              void* d_out, int out_size)
{
    const float* img   = (const float*)d_in[0];
    const int*   caps  = (const int*)  d_in[1];
    const float* Wh1   = (const float*)d_in[2];
    const float* bh1   = (const float*)d_in[3];
    const float* Wh2   = (const float*)d_in[4];
    const float* bh2   = (const float*)d_in[5];
    const float* Wc1   = (const float*)d_in[6];
    const float* bc1   = (const float*)d_in[7];
    const float* Wc2   = (const float*)d_in[8];
    const float* bc2   = (const float*)d_in[9];
    const float* emb   = (const float*)d_in[10];
    const float* Wih0f = (const float*)d_in[11];
    const float* Whh0f = (const float*)d_in[12];
    const float* b0f   = (const float*)d_in[13];
    const float* Wih0b = (const float*)d_in[14];
    const float* Whh0b = (const float*)d_in[15];
    const float* b0b   = (const float*)d_in[16];
    const float* Wih1f = (const float*)d_in[17];
    const float* Whh1f = (const float*)d_in[18];
    const float* b1f   = (const float*)d_in[19];
    const float* Wih1b = (const float*)d_in[20];
    const float* Whh1b = (const float*)d_in[21];
    const float* b1b   = (const float*)d_in[22];
    const float* Wfc   = (const float*)d_in[23];
    const float* bfc   = (const float*)d_in[24];
    float* outp = (float*)d_out;

    float *p_W0T, *p_W1T;
    cudaGetSymbolAddress((void**)&p_W0T,  g_W0T);
    cudaGetSymbolAddress((void**)&p_W1T,  g_W1T);

    const size_t W1ROW = (size_t)H4 * (Hc + H2);

    // Launch 0: transposes + MLP stage1 + gather + convB
    TParams6 tp;
    tp.p[0] = { Whh0f, p_W0T,                 Hc, Hc };
    tp.p[1] = { Whh0b, p_W0T + (size_t)H4*Hc, Hc, Hc };
    tp.p[2] = { Whh1f, p_W1T,                 Hc, Hc + H2 };
    tp.p[3] = { Wih1f, p_W1T + Hc,            H2, Hc + H2 };
    tp.p[4] = { Whh1b, p_W1T + W1ROW,         Hc, Hc + H2 };
    tp.p[5] = { Wih1b, p_W1T + W1ROW + Hc,    H2, Hc + H2 };
    pre1<<<P1_TOTAL, 256>>>(tp, img, Wh1, bh1, Wc1, bc1, caps, emb, Wfc);

    // Launch 1: fragment-linear split-bf16 recurrent weights
    wfrag<<<(262144 + 786432) / 256, 256>>>();

    // Launch 2: MLP stage2 (dual)
    pre2k<<<dim3(Hc/64, 1, 2), 256>>>(Wh2, bh2, Wc2, bc2);

    // Launch 3: xg0 GEMMs + b-major state broadcast
    pre3<<<dim3(H4/128, (NTB+127)/128, 3), 256>>>(Wih0f, b0f, Wih0b, b0b);

    // Launch 4: persistent recurrent chain (TC stage B, 16 warps) + fused convA
    cudaFuncSetAttribute(lstm_persist, cudaFuncAttributeMaxDynamicSharedMemorySize, LSTM_SMEM);
    lstm_persist<<<NBLK, LTH, LSTM_SMEM>>>(b1f, b1b);

    // Launch 5: tensor-core FC
    cudaFuncSetAttribute(fc_wmma, cudaFuncAttributeMaxDynamicSharedMemorySize, FC_SMEM);
    fc_wmma<<<dim3((Vc + FCBN - 1)/FCBN, (NTB + FCBM - 1)/FCBM), 256, FC_SMEM>>>(bfc, outp);
}